// round 9
// baseline (speedup 1.0000x reference)
#include <cuda_runtime.h>
#include <cuda_fp16.h>
#include <cstdint>

#define NDOM 4
#define NB   8192
#define NF   128
#define BM   128
#define BN   128
#define NT   (NB / BN)
#define NTHREADS 512
#define MARGIN 0.045f
#define MAXFLAGS 8192

// ---------------- SMEM layout (byte offsets) ----------------
#define OFF_A   0u            /* A fp16 32KB (swizzled row-major) */
#define OFF_B   32768u        /* buf b at OFF_B + b*32768 */
#define OFF_SCR 98304u        /* [128 rows][4 wn][8 floats] = 16KB */
#define SMEM_BYTES 114688u

__device__ int g_labels[NDOM * NB];
__device__ int g_flag_cnt;
__device__ int g_flags[MAXFLAGS];
__device__ unsigned long long g_best[MAXFLAGS];
__device__ __half g_half[NDOM * NB * NF];   // 8 MB

// ---------------- helpers ----------------
__device__ __forceinline__ uint32_t smem_u32(const void* p) {
    uint32_t a;
    asm("{ .reg .u64 t; cvta.to.shared.u64 t, %1; cvt.u32.u64 %0, t; }"
        : "=r"(a) : "l"(p));
    return a;
}
__device__ __forceinline__ uint32_t fkey(float v) {
    uint32_t u = __float_as_uint(v);
    return (u & 0x80000000u) ? ~u : (u | 0x80000000u);
}
__device__ __forceinline__ void ldsm4(uint32_t* r, uint32_t addr) {
    asm volatile("ldmatrix.sync.aligned.m8n8.x4.shared.b16 {%0,%1,%2,%3}, [%4];"
                 : "=r"(r[0]), "=r"(r[1]), "=r"(r[2]), "=r"(r[3]) : "r"(addr));
}
__device__ __forceinline__ void mma16816(float* d, const uint32_t* a,
                                         const uint32_t* b) {
    asm volatile(
        "mma.sync.aligned.m16n8k16.row.col.f32.f16.f16.f32 "
        "{%0,%1,%2,%3}, {%4,%5,%6,%7}, {%8,%9}, {%0,%1,%2,%3};"
        : "+f"(d[0]), "+f"(d[1]), "+f"(d[2]), "+f"(d[3])
        : "r"(a[0]), "r"(a[1]), "r"(a[2]), "r"(a[3]), "r"(b[0]), "r"(b[1]));
}
#define CP_ASYNC(dst, src) \
    asm volatile("cp.async.cg.shared.global [%0], [%1], 16;" :: "r"(dst), "l"(src))
#define CP_COMMIT() asm volatile("cp.async.commit_group;" ::: "memory")
#define CP_WAIT1()  asm volatile("cp.async.wait_group 1;" ::: "memory")
#define CP_WAIT0()  asm volatile("cp.async.wait_group 0;" ::: "memory")

// Copy one 128x128 fp16 tile gmem -> swizzled smem via cp.async.
// byte(row,k) = row*256 + ((2k) ^ ((row&7)<<4)); 16B chunk = 8 k.
__device__ __forceinline__ void copy_tile_async(
    uint32_t smem_dst, const __half* __restrict__ g, int tid) {
#pragma unroll
    for (int it = 0; it < 4; ++it) {
        const int rem = it * NTHREADS + tid;   // 0..2047
        const int row = rem >> 4;
        const int kc = rem & 15;
        const uint32_t dstb = (uint32_t)row * 256u
            + (((uint32_t)kc * 16u) ^ (((uint32_t)row & 7u) << 4));
        CP_ASYNC(smem_dst + dstb, g + row * NF + kc * 8);
    }
}

#define MERGE_MIN(P1, P2, I1, q1, q2, qi) \
    do { if ((q1) < (P1)) { P2 = fminf(P1, q2); P1 = q1; I1 = qi; } \
         else { P2 = fminf(P2, q1); } } while (0)
#define MERGE_MAX(N1, N2, J1, m1, m2, mi) \
    do { if ((m1) > (N1)) { N2 = fmaxf(N1, m2); N1 = m1; J1 = mi; } \
         else { N2 = fmaxf(N2, m1); } } while (0)

// ---------------- one-shot fp32 -> fp16 ----------------
__global__ void split_kernel(const float* __restrict__ emb) {
    const int i = blockIdx.x * blockDim.x + threadIdx.x;
    const float4 v = reinterpret_cast<const float4*>(emb)[i];
    uint2 hv;
    hv.x = ((uint32_t)__half_as_ushort(__float2half_rn(v.x)))
         | ((uint32_t)__half_as_ushort(__float2half_rn(v.y)) << 16);
    hv.y = ((uint32_t)__half_as_ushort(__float2half_rn(v.z)))
         | ((uint32_t)__half_as_ushort(__float2half_rn(v.w)) << 16);
    reinterpret_cast<uint2*>(g_half)[i] = hv;
}

// ---------------- label normalization + flag reset ----------------
__global__ void convert_labels_kernel(const unsigned int* __restrict__ w, int n) {
    __shared__ int s_any;
    if (threadIdx.x == 0) { s_any = 0; g_flag_cnt = 0; }
    __syncthreads();
    int any = 0;
    for (int i = threadIdx.x; i < n / 2; i += blockDim.x)
        any |= (w[2 * i + 1] != 0u);
    if (any) atomicOr(&s_any, 1);
    for (int i = threadIdx.x; i < MAXFLAGS; i += blockDim.x) g_best[i] = 0ull;
    __syncthreads();
    const bool is64 = (s_any == 0);
    for (int i = threadIdx.x; i < n; i += blockDim.x)
        g_labels[i] = is64 ? (int)w[2 * i] : (int)w[i];
}

// ---------------- fused single-pass HMMA GEMM + top-2 mining ----------------
__global__ __launch_bounds__(NTHREADS, 1)
void mine_kernel(const float* __restrict__ emb,
                 float* __restrict__ pos_dist, float* __restrict__ neg_dist,
                 float* __restrict__ pos_embed, float* __restrict__ neg_embed) {
    extern __shared__ char smem[];
    const uint32_t sb = smem_u32(smem);
    const int tid = threadIdx.x;
    const int w = tid >> 5, L = tid & 31;
    const int wm = w & 3, wn = w >> 2;          // 4x4 warp grid
    const int d = blockIdx.y;
    const int tb = blockIdx.x * BM;

    const float* __restrict__ embd = emb + (size_t)d * NB * NF;
    const __half* __restrict__ gh = g_half + (size_t)d * NB * NF;
    const int* __restrict__ labd = g_labels + d * NB;

    // prologue: A tile (resident) + B tile 0
    copy_tile_async(sb + OFF_A, gh + (size_t)tb * NF, tid);
    copy_tile_async(sb + OFF_B, gh, tid);
    CP_COMMIT();

    const uint32_t cxA = ((uint32_t)(L >> 4) * 16u) ^ (((uint32_t)L & 7u) << 4);
    const uint32_t cxB = ((uint32_t)((L >> 3) & 1) * 16u) ^ (((uint32_t)L & 7u) << 4);
    uint32_t aBase[2];
#pragma unroll
    for (int mt = 0; mt < 2; ++mt) {
        const int rowA = wm * 32 + mt * 16 + (L & 7) + ((L >> 3) & 1) * 8;
        aBase[mt] = sb + OFF_A + (uint32_t)rowA * 256u;
    }
    uint32_t bRow[2];
#pragma unroll
    for (int bi = 0; bi < 2; ++bi) {
        const int rowB = wn * 32 + bi * 16 + (L & 7) + (L >> 4) * 8;
        bRow[bi] = (uint32_t)rowB * 256u;
    }

    // this thread's 4 result rows: row(s) = rbase + (s&1)*8 + (s>>1)*16
    const int rbase = wm * 32 + (L >> 2);
    int li[4];
#pragma unroll
    for (int s = 0; s < 4; ++s)
        li[s] = labd[tb + rbase + (s & 1) * 8 + (s >> 1) * 16];

    const float INF = __int_as_float(0x7f800000);
    float p1[4], p2[4], n1[4], n2[4];
    int i1[4], j1[4];
#pragma unroll
    for (int s = 0; s < 4; ++s) {
        p1[s] = INF; p2[s] = INF; n1[s] = -INF; n2[s] = -INF;
        i1[s] = -1; j1[s] = -1;
    }

    for (int t = 0; t < NT; ++t) {
        if (t + 1 < NT) {
            copy_tile_async(sb + OFF_B + (uint32_t)((t + 1) & 1) * 32768u,
                            gh + (size_t)(t + 1) * BN * NF, tid);
            CP_COMMIT();
            CP_WAIT1();
        } else {
            CP_WAIT0();
        }
        __syncthreads();

        const int jb = t * BN + wn * 32 + (L & 3) * 2;
        int labc[4][2];
#pragma unroll
        for (int nt = 0; nt < 4; ++nt) {
            const int2 lv = *reinterpret_cast<const int2*>(labd + jb + nt * 8);
            labc[nt][0] = lv.x; labc[nt][1] = lv.y;
        }

        float acc[2][4][4];
#pragma unroll
        for (int mt = 0; mt < 2; ++mt)
#pragma unroll
            for (int nt = 0; nt < 4; ++nt)
#pragma unroll
                for (int r = 0; r < 4; ++r) acc[mt][nt][r] = 0.0f;

        const uint32_t sbB = sb + OFF_B + (uint32_t)(t & 1) * 32768u;
#pragma unroll
        for (int ks = 0; ks < 8; ++ks) {
            const uint32_t offA = ((uint32_t)ks * 32u) ^ cxA;
            const uint32_t offB = ((uint32_t)ks * 32u) ^ cxB;
            uint32_t A[2][4], B[2][4];
            ldsm4(A[0], aBase[0] + offA);
            ldsm4(A[1], aBase[1] + offA);
            ldsm4(B[0], sbB + bRow[0] + offB);
            ldsm4(B[1], sbB + bRow[1] + offB);
#pragma unroll
            for (int bi = 0; bi < 2; ++bi)
#pragma unroll
                for (int mt = 0; mt < 2; ++mt) {
                    mma16816(acc[mt][2 * bi],     A[mt], B[bi]);
                    mma16816(acc[mt][2 * bi + 1], A[mt], B[bi] + 2);
                }
        }

        // fused top-2 mining from register accumulators
#pragma unroll
        for (int nt = 0; nt < 4; ++nt)
#pragma unroll
            for (int e = 0; e < 2; ++e) {
                const int lj = labc[nt][e];
                const int j = jb + nt * 8 + e;
#pragma unroll
                for (int s = 0; s < 4; ++s) {
                    const float v = acc[s >> 1][nt][(s & 1) * 2 + e];
                    if (lj == li[s]) {
                        const int growr = tb + rbase + (s & 1) * 8 + (s >> 1) * 16;
                        if (j != growr) {
                            if (v < p1[s]) { p2[s] = p1[s]; p1[s] = v; i1[s] = j; }
                            else if (v < p2[s]) p2[s] = v;
                        }
                    } else {
                        if (v > n1[s]) { n2[s] = n1[s]; n1[s] = v; j1[s] = j; }
                        else if (v > n2[s]) n2[s] = v;
                    }
                }
            }
        __syncthreads();
    }

    // reduce across the 4 lanes sharing each row (shfl offsets 1,2)
#pragma unroll
    for (int s = 0; s < 4; ++s) {
#pragma unroll
        for (int off = 1; off <= 2; off <<= 1) {
            const float q1 = __shfl_xor_sync(~0u, p1[s], off);
            const float q2 = __shfl_xor_sync(~0u, p2[s], off);
            const int   qi = __shfl_xor_sync(~0u, i1[s], off);
            const float m1 = __shfl_xor_sync(~0u, n1[s], off);
            const float m2 = __shfl_xor_sync(~0u, n2[s], off);
            const int   mi = __shfl_xor_sync(~0u, j1[s], off);
            MERGE_MIN(p1[s], p2[s], i1[s], q1, q2, qi);
            MERGE_MAX(n1[s], n2[s], j1[s], m1, m2, mi);
        }
    }

    // merge 4 warp-columns via scratch [row][wn][8]
    float* scr = reinterpret_cast<float*>(smem + OFF_SCR);
    if (wn > 0 && (L & 3) == 0) {
#pragma unroll
        for (int s = 0; s < 4; ++s) {
            const int row = rbase + (s & 1) * 8 + (s >> 1) * 16;
            float* sr = scr + (row * 4 + wn) * 8;
            sr[0] = p1[s]; sr[1] = p2[s];
            reinterpret_cast<int*>(sr)[2] = i1[s];
            sr[3] = n1[s]; sr[4] = n2[s];
            reinterpret_cast<int*>(sr)[5] = j1[s];
        }
    }
    __syncthreads();
    if (wn == 0 && (L & 3) == 0) {
#pragma unroll
        for (int s = 0; s < 4; ++s) {
            const int row = rbase + (s & 1) * 8 + (s >> 1) * 16;
            float P1 = p1[s], P2 = p2[s], N1 = n1[s], N2 = n2[s];
            int I1 = i1[s], J1 = j1[s];
#pragma unroll
            for (int o = 1; o < 4; ++o) {
                const float* sr = scr + (row * 4 + o) * 8;
                MERGE_MIN(P1, P2, I1, sr[0], sr[1], reinterpret_cast<const int*>(sr)[2]);
                MERGE_MAX(N1, N2, J1, sr[3], sr[4], reinterpret_cast<const int*>(sr)[5]);
            }
            const bool has_pos = (P1 < INF);
            const size_t go = (size_t)d * NB + tb + row;
            pos_dist[go] = has_pos ? P1 : 0.0f;
            neg_dist[go] = has_pos ? N1 : 0.0f;
            reinterpret_cast<int*>(scr)[(row * 4) * 8 + 6] = has_pos ? I1 : -1;
            reinterpret_cast<int*>(scr)[(row * 4) * 8 + 7] = has_pos ? J1 : -1;
            if (has_pos) {
                const int basec = (int)((d * NB + tb + row) << 1);
                if (P2 - P1 < MARGIN) {
                    const int x = atomicAdd(&g_flag_cnt, 1);
                    if (x < MAXFLAGS) g_flags[x] = basec | 0;
                }
                if (N1 - N2 < MARGIN) {
                    const int x = atomicAdd(&g_flag_cnt, 1);
                    if (x < MAXFLAGS) g_flags[x] = basec | 1;
                }
            }
        }
    }
    __syncthreads();

    // cooperative embedding gather: copy c = row*2 + side, one warp per copy
    for (int c = w; c < 256; c += 16) {
        const int row = c >> 1, side = c & 1;
        const int idx = reinterpret_cast<int*>(scr)[(row * 4) * 8 + 6 + side];
        float4* dst = reinterpret_cast<float4*>(
            (side ? neg_embed : pos_embed) + ((size_t)d * NB + tb + row) * NF);
        if (idx >= 0)
            dst[L] = reinterpret_cast<const float4*>(embd + (size_t)idx * NF)[L];
        else
            dst[L] = make_float4(0.f, 0.f, 0.f, 0.f);
    }
}

// ---------------- exact refine (persistent grids) ----------------
__global__ void refine_scan_kernel(const float* __restrict__ emb) {
    __shared__ float srow[NF];
    __shared__ int sli;
    __shared__ unsigned long long swb[8];
    const int cnt = min(g_flag_cnt, MAXFLAGS);
    for (int f = blockIdx.x; f < cnt; f += gridDim.x) {
        const int code = g_flags[f];
        const int side = code & 1, gr = code >> 1;
        const int d = gr >> 13, row = gr & (NB - 1);
        const float* __restrict__ embd = emb + (size_t)d * NB * NF;
        __syncthreads();
        if (threadIdx.x < NF) srow[threadIdx.x] = embd[(size_t)row * NF + threadIdx.x];
        if (threadIdx.x == 0) sli = g_labels[d * NB + row];
        __syncthreads();
        const int li = sli;
        const float4* a4 = reinterpret_cast<const float4*>(srow);

        unsigned long long best = 0ull;
        for (int j = threadIdx.x; j < NB; j += blockDim.x) {
            const int lj = g_labels[d * NB + j];
            const bool valid = side ? (lj != li) : (lj == li && j != row);
            if (!valid) continue;
            const float4* b4 = reinterpret_cast<const float4*>(embd + (size_t)j * NF);
            float accv = 0.0f;
#pragma unroll
            for (int qq = 0; qq < 32; ++qq) {
                const float4 av = a4[qq], bv = b4[qq];
                accv = fmaf(av.x, bv.x, accv);
                accv = fmaf(av.y, bv.y, accv);
                accv = fmaf(av.z, bv.z, accv);
                accv = fmaf(av.w, bv.w, accv);
            }
            uint32_t key = fkey(accv);
            if (!side) key = ~key;
            const unsigned long long pk =
                ((unsigned long long)key << 32) | (uint32_t)(NB - 1 - j);
            if (pk > best) best = pk;
        }
#pragma unroll
        for (int off = 16; off > 0; off >>= 1) {
            const unsigned long long o = __shfl_xor_sync(~0u, best, off);
            if (o > best) best = o;
        }
        if ((threadIdx.x & 31) == 0) swb[threadIdx.x >> 5] = best;
        __syncthreads();
        if (threadIdx.x == 0) {
            unsigned long long b = swb[0];
#pragma unroll
            for (int o = 1; o < 8; ++o) if (swb[o] > b) b = swb[o];
            g_best[f] = b;
        }
    }
}

__global__ void refine_write_kernel(const float* __restrict__ emb,
                                    float* __restrict__ pos_dist,
                                    float* __restrict__ neg_dist,
                                    float* __restrict__ pos_embed,
                                    float* __restrict__ neg_embed) {
    const int cnt = min(g_flag_cnt, MAXFLAGS);
    for (int f = blockIdx.x; f < cnt; f += gridDim.x) {
        const int code = g_flags[f];
        const int side = code & 1, gr = code >> 1;
        const int d = gr >> 13, row = gr & (NB - 1);
        const unsigned long long pk = g_best[f];
        const uint32_t key = (uint32_t)(pk >> 32);
        const int j = NB - 1 - (int)(pk & 0xFFFFFFFFull);
        const uint32_t m = side ? key : ~key;
        const uint32_t u = (m & 0x80000000u) ? (m & 0x7FFFFFFFu) : ~m;
        const float v = __uint_as_float(u);

        const size_t go = (size_t)d * NB + row;
        float* dist = side ? neg_dist : pos_dist;
        float* embo = side ? neg_embed : pos_embed;
        if (threadIdx.x == 0) dist[go] = v;
        embo[go * NF + threadIdx.x] = emb[((size_t)d * NB + j) * NF + threadIdx.x];
    }
}

// ---------------- launch ----------------
extern "C" void kernel_launch(void* const* d_in, const int* in_sizes, int n_in,
                              void* d_out, int out_size) {
    (void)in_sizes; (void)n_in; (void)out_size;
    const float* emb = (const float*)d_in[0];
    const unsigned int* labw = (const unsigned int*)d_in[1];

    float* out = (float*)d_out;
    float* pos_dist  = out;
    float* neg_dist  = out + (size_t)NDOM * NB;
    float* pos_embed = out + (size_t)2 * NDOM * NB;
    float* neg_embed = pos_embed + (size_t)NDOM * NB * NF;

    convert_labels_kernel<<<1, 256>>>(labw, NDOM * NB);
    split_kernel<<<(NDOM * NB * NF / 4) / 256, 256>>>(emb);

    cudaFuncSetAttribute(mine_kernel,
                         cudaFuncAttributeMaxDynamicSharedMemorySize, SMEM_BYTES);
    dim3 grid(NB / BM, NDOM);
    mine_kernel<<<grid, NTHREADS, SMEM_BYTES>>>(emb, pos_dist, neg_dist,
                                                pos_embed, neg_embed);

    refine_scan_kernel<<<256, 256>>>(emb);
    refine_write_kernel<<<128, NF>>>(emb, pos_dist, neg_dist,
                                     pos_embed, neg_embed);
}

// round 10
// speedup vs baseline: 1.9484x; 1.9484x over previous
#include <cuda_runtime.h>
#include <cuda_fp16.h>
#include <cstdint>

#define NDOM 4
#define NB   8192
#define NF   128
#define BM   128
#define BN   128
#define NT   (NB / BN)
#define NTHREADS 512
#define MARGIN1 0.022f
#define MARGIN2 2e-4f
#define MAXF  4096             /* per-domain L1 flags */
#define MAXF3 2048             /* L3 flags */
#define NSLICE 8

// ---------------- SMEM layouts ----------------
// mine kernel
#define OFF_A   0u
#define OFF_B   32768u
#define OFF_SCR 98304u
#define SMEM_BYTES 114688u
// refine2 kernel
#define R_AH   0u
#define R_AL   32768u
#define R_B    65536u          /* buf b at R_B + b*65536: hi, lo at +32768 */
#define R_SCR  196608u
#define R_ROWS 212992u
#define R_LABS 213504u
#define SMEM2_BYTES 214016u

__device__ int g_labels[NDOM * NB];
__device__ int g_fcnt[NDOM];
__device__ int g_flags1[NDOM * MAXF];
__device__ int g_fcnt3;
__device__ int g_flags3[MAXF3];
__device__ unsigned long long g_best[MAXF3];
__device__ __half g_hi[NDOM * NB * NF];
__device__ __half g_lo[NDOM * NB * NF];
// L2 partials: [d][flag][slice][8 floats]
__device__ float g_rp[(size_t)NDOM * MAXF * NSLICE * 8];

// ---------------- helpers ----------------
__device__ __forceinline__ uint32_t smem_u32(const void* p) {
    uint32_t a;
    asm("{ .reg .u64 t; cvta.to.shared.u64 t, %1; cvt.u32.u64 %0, t; }"
        : "=r"(a) : "l"(p));
    return a;
}
__device__ __forceinline__ uint32_t fkey(float v) {
    uint32_t u = __float_as_uint(v);
    return (u & 0x80000000u) ? ~u : (u | 0x80000000u);
}
__device__ __forceinline__ void ldsm4(uint32_t* r, uint32_t addr) {
    asm volatile("ldmatrix.sync.aligned.m8n8.x4.shared.b16 {%0,%1,%2,%3}, [%4];"
                 : "=r"(r[0]), "=r"(r[1]), "=r"(r[2]), "=r"(r[3]) : "r"(addr));
}
__device__ __forceinline__ void mma16816(float* d, const uint32_t* a,
                                         const uint32_t* b) {
    asm volatile(
        "mma.sync.aligned.m16n8k16.row.col.f32.f16.f16.f32 "
        "{%0,%1,%2,%3}, {%4,%5,%6,%7}, {%8,%9}, {%0,%1,%2,%3};"
        : "+f"(d[0]), "+f"(d[1]), "+f"(d[2]), "+f"(d[3])
        : "r"(a[0]), "r"(a[1]), "r"(a[2]), "r"(a[3]), "r"(b[0]), "r"(b[1]));
}
#define CP_ASYNC(dst, src) \
    asm volatile("cp.async.cg.shared.global [%0], [%1], 16;" :: "r"(dst), "l"(src))
#define CP_COMMIT() asm volatile("cp.async.commit_group;" ::: "memory")
#define CP_WAIT1()  asm volatile("cp.async.wait_group 1;" ::: "memory")
#define CP_WAIT0()  asm volatile("cp.async.wait_group 0;" ::: "memory")

__device__ __forceinline__ void copy_tile_async(
    uint32_t smem_dst, const __half* __restrict__ g, int tid) {
#pragma unroll
    for (int it = 0; it < 4; ++it) {
        const int rem = it * NTHREADS + tid;
        const int row = rem >> 4;
        const int kc = rem & 15;
        const uint32_t dstb = (uint32_t)row * 256u
            + (((uint32_t)kc * 16u) ^ (((uint32_t)row & 7u) << 4));
        CP_ASYNC(smem_dst + dstb, g + row * NF + kc * 8);
    }
}

#define MERGE_MIN(P1, P2, I1, q1, q2, qi) \
    do { if ((q1) < (P1)) { P2 = fminf(P1, q2); P1 = q1; I1 = qi; } \
         else { P2 = fminf(P2, q1); } } while (0)
#define MERGE_MAX(N1, N2, J1, m1, m2, mi) \
    do { if ((m1) > (N1)) { N2 = fmaxf(N1, m2); N1 = m1; J1 = mi; } \
         else { N2 = fmaxf(N2, m1); } } while (0)

// ---------------- one-shot fp32 -> fp16 hi/lo split ----------------
__global__ void split_kernel(const float* __restrict__ emb) {
    const int i = blockIdx.x * blockDim.x + threadIdx.x;
    const float4 v = reinterpret_cast<const float4*>(emb)[i];
    const __half hx = __float2half_rn(v.x), hy = __float2half_rn(v.y);
    const __half hz = __float2half_rn(v.z), hw = __float2half_rn(v.w);
    const __half lx = __float2half_rn(v.x - __half2float(hx));
    const __half ly = __float2half_rn(v.y - __half2float(hy));
    const __half lz = __float2half_rn(v.z - __half2float(hz));
    const __half lw = __float2half_rn(v.w - __half2float(hw));
    uint2 hv, lv;
    hv.x = ((uint32_t)__half_as_ushort(hx)) | ((uint32_t)__half_as_ushort(hy) << 16);
    hv.y = ((uint32_t)__half_as_ushort(hz)) | ((uint32_t)__half_as_ushort(hw) << 16);
    lv.x = ((uint32_t)__half_as_ushort(lx)) | ((uint32_t)__half_as_ushort(ly) << 16);
    lv.y = ((uint32_t)__half_as_ushort(lz)) | ((uint32_t)__half_as_ushort(lw) << 16);
    reinterpret_cast<uint2*>(g_hi)[i] = hv;
    reinterpret_cast<uint2*>(g_lo)[i] = lv;
}

// ---------------- label normalization + counters reset ----------------
__global__ void convert_labels_kernel(const unsigned int* __restrict__ w, int n) {
    __shared__ int s_any;
    if (threadIdx.x == 0) { s_any = 0; g_fcnt3 = 0; }
    if (threadIdx.x < NDOM) g_fcnt[threadIdx.x] = 0;
    __syncthreads();
    int any = 0;
    for (int i = threadIdx.x; i < n / 2; i += blockDim.x)
        any |= (w[2 * i + 1] != 0u);
    if (any) atomicOr(&s_any, 1);
    for (int i = threadIdx.x; i < MAXF3; i += blockDim.x) g_best[i] = 0ull;
    __syncthreads();
    const bool is64 = (s_any == 0);
    for (int i = threadIdx.x; i < n; i += blockDim.x)
        g_labels[i] = is64 ? (int)w[2 * i] : (int)w[i];
}

// ---------------- L1: fused single-pass HMMA GEMM + top-2 mining ----------------
__global__ __launch_bounds__(NTHREADS, 1)
void mine_kernel(const float* __restrict__ emb,
                 float* __restrict__ pos_dist, float* __restrict__ neg_dist,
                 float* __restrict__ pos_embed, float* __restrict__ neg_embed) {
    extern __shared__ char smem[];
    const uint32_t sb = smem_u32(smem);
    const int tid = threadIdx.x;
    const int w = tid >> 5, L = tid & 31;
    const int wm = w & 3, wn = w >> 2;
    const int d = blockIdx.y;
    const int tb = blockIdx.x * BM;

    const float* __restrict__ embd = emb + (size_t)d * NB * NF;
    const __half* __restrict__ gh = g_hi + (size_t)d * NB * NF;
    const int* __restrict__ labd = g_labels + d * NB;

    copy_tile_async(sb + OFF_A, gh + (size_t)tb * NF, tid);
    copy_tile_async(sb + OFF_B, gh, tid);
    CP_COMMIT();

    const uint32_t cxA = ((uint32_t)(L >> 4) * 16u) ^ (((uint32_t)L & 7u) << 4);
    const uint32_t cxB = ((uint32_t)((L >> 3) & 1) * 16u) ^ (((uint32_t)L & 7u) << 4);
    uint32_t aBase[2];
#pragma unroll
    for (int mt = 0; mt < 2; ++mt) {
        const int rowA = wm * 32 + mt * 16 + (L & 7) + ((L >> 3) & 1) * 8;
        aBase[mt] = sb + OFF_A + (uint32_t)rowA * 256u;
    }
    uint32_t bRow[2];
#pragma unroll
    for (int bi = 0; bi < 2; ++bi) {
        const int rowB = wn * 32 + bi * 16 + (L & 7) + (L >> 4) * 8;
        bRow[bi] = (uint32_t)rowB * 256u;
    }

    const int rbase = wm * 32 + (L >> 2);
    int li[4];
#pragma unroll
    for (int s = 0; s < 4; ++s)
        li[s] = labd[tb + rbase + (s & 1) * 8 + (s >> 1) * 16];

    const float INF = __int_as_float(0x7f800000);
    float p1[4], p2[4], n1[4], n2[4];
    int i1[4], j1[4];
#pragma unroll
    for (int s = 0; s < 4; ++s) {
        p1[s] = INF; p2[s] = INF; n1[s] = -INF; n2[s] = -INF;
        i1[s] = -1; j1[s] = -1;
    }

    for (int t = 0; t < NT; ++t) {
        if (t + 1 < NT) {
            copy_tile_async(sb + OFF_B + (uint32_t)((t + 1) & 1) * 32768u,
                            gh + (size_t)(t + 1) * BN * NF, tid);
            CP_COMMIT();
            CP_WAIT1();
        } else {
            CP_WAIT0();
        }
        __syncthreads();

        const int jb = t * BN + wn * 32 + (L & 3) * 2;
        int labc[4][2];
#pragma unroll
        for (int nt = 0; nt < 4; ++nt) {
            const int2 lv = *reinterpret_cast<const int2*>(labd + jb + nt * 8);
            labc[nt][0] = lv.x; labc[nt][1] = lv.y;
        }

        float acc[2][4][4];
#pragma unroll
        for (int mt = 0; mt < 2; ++mt)
#pragma unroll
            for (int nt = 0; nt < 4; ++nt)
#pragma unroll
                for (int r = 0; r < 4; ++r) acc[mt][nt][r] = 0.0f;

        const uint32_t sbB = sb + OFF_B + (uint32_t)(t & 1) * 32768u;
#pragma unroll
        for (int ks = 0; ks < 8; ++ks) {
            const uint32_t offA = ((uint32_t)ks * 32u) ^ cxA;
            const uint32_t offB = ((uint32_t)ks * 32u) ^ cxB;
            uint32_t A[2][4], B[2][4];
            ldsm4(A[0], aBase[0] + offA);
            ldsm4(A[1], aBase[1] + offA);
            ldsm4(B[0], sbB + bRow[0] + offB);
            ldsm4(B[1], sbB + bRow[1] + offB);
#pragma unroll
            for (int bi = 0; bi < 2; ++bi)
#pragma unroll
                for (int mt = 0; mt < 2; ++mt) {
                    mma16816(acc[mt][2 * bi],     A[mt], B[bi]);
                    mma16816(acc[mt][2 * bi + 1], A[mt], B[bi] + 2);
                }
        }

#pragma unroll
        for (int nt = 0; nt < 4; ++nt)
#pragma unroll
            for (int e = 0; e < 2; ++e) {
                const int lj = labc[nt][e];
                const int j = jb + nt * 8 + e;
#pragma unroll
                for (int s = 0; s < 4; ++s) {
                    const float v = acc[s >> 1][nt][(s & 1) * 2 + e];
                    if (lj == li[s]) {
                        const int growr = tb + rbase + (s & 1) * 8 + (s >> 1) * 16;
                        if (j != growr) {
                            if (v < p1[s]) { p2[s] = p1[s]; p1[s] = v; i1[s] = j; }
                            else if (v < p2[s]) p2[s] = v;
                        }
                    } else {
                        if (v > n1[s]) { n2[s] = n1[s]; n1[s] = v; j1[s] = j; }
                        else if (v > n2[s]) n2[s] = v;
                    }
                }
            }
        __syncthreads();
    }

#pragma unroll
    for (int s = 0; s < 4; ++s) {
#pragma unroll
        for (int off = 1; off <= 2; off <<= 1) {
            const float q1 = __shfl_xor_sync(~0u, p1[s], off);
            const float q2 = __shfl_xor_sync(~0u, p2[s], off);
            const int   qi = __shfl_xor_sync(~0u, i1[s], off);
            const float m1 = __shfl_xor_sync(~0u, n1[s], off);
            const float m2 = __shfl_xor_sync(~0u, n2[s], off);
            const int   mi = __shfl_xor_sync(~0u, j1[s], off);
            MERGE_MIN(p1[s], p2[s], i1[s], q1, q2, qi);
            MERGE_MAX(n1[s], n2[s], j1[s], m1, m2, mi);
        }
    }

    float* scr = reinterpret_cast<float*>(smem + OFF_SCR);
    if (wn > 0 && (L & 3) == 0) {
#pragma unroll
        for (int s = 0; s < 4; ++s) {
            const int row = rbase + (s & 1) * 8 + (s >> 1) * 16;
            float* sr = scr + (row * 4 + wn) * 8;
            sr[0] = p1[s]; sr[1] = p2[s];
            reinterpret_cast<int*>(sr)[2] = i1[s];
            sr[3] = n1[s]; sr[4] = n2[s];
            reinterpret_cast<int*>(sr)[5] = j1[s];
        }
    }
    __syncthreads();
    if (wn == 0 && (L & 3) == 0) {
#pragma unroll
        for (int s = 0; s < 4; ++s) {
            const int row = rbase + (s & 1) * 8 + (s >> 1) * 16;
            float P1 = p1[s], P2 = p2[s], N1 = n1[s], N2 = n2[s];
            int I1 = i1[s], J1 = j1[s];
#pragma unroll
            for (int o = 1; o < 4; ++o) {
                const float* sr = scr + (row * 4 + o) * 8;
                MERGE_MIN(P1, P2, I1, sr[0], sr[1], reinterpret_cast<const int*>(sr)[2]);
                MERGE_MAX(N1, N2, J1, sr[3], sr[4], reinterpret_cast<const int*>(sr)[5]);
            }
            const bool has_pos = (P1 < INF);
            const size_t go = (size_t)d * NB + tb + row;
            pos_dist[go] = has_pos ? P1 : 0.0f;
            neg_dist[go] = has_pos ? N1 : 0.0f;
            reinterpret_cast<int*>(scr)[(row * 4) * 8 + 6] = has_pos ? I1 : -1;
            reinterpret_cast<int*>(scr)[(row * 4) * 8 + 7] = has_pos ? J1 : -1;
            if (has_pos) {
                const int code = (tb + row) << 1;
                if (P2 - P1 < MARGIN1) {
                    const int x = atomicAdd(&g_fcnt[d], 1);
                    if (x < MAXF) g_flags1[d * MAXF + x] = code | 0;
                }
                if (N1 - N2 < MARGIN1) {
                    const int x = atomicAdd(&g_fcnt[d], 1);
                    if (x < MAXF) g_flags1[d * MAXF + x] = code | 1;
                }
            }
        }
    }
    __syncthreads();

    for (int c = w; c < 256; c += 16) {
        const int row = c >> 1, side = c & 1;
        const int idx = reinterpret_cast<int*>(scr)[(row * 4) * 8 + 6 + side];
        float4* dst = reinterpret_cast<float4*>(
            (side ? neg_embed : pos_embed) + ((size_t)d * NB + tb + row) * NF);
        if (idx >= 0)
            dst[L] = reinterpret_cast<const float4*>(embd + (size_t)idx * NF)[L];
        else
            dst[L] = make_float4(0.f, 0.f, 0.f, 0.f);
    }
}

// ---------------- L2: batched 3-pass MMA refine over flagged rows ----------------
__global__ __launch_bounds__(NTHREADS, 1)
void refine2_kernel() {
    extern __shared__ char smem[];
    const uint32_t sb = smem_u32(smem);
    const int tid = threadIdx.x;
    const int w = tid >> 5, L = tid & 31;
    const int wm = w & 3, wn = w >> 2;
    const int d = blockIdx.z, grp = blockIdx.x, slice = blockIdx.y;

    const int cnt = min(g_fcnt[d], MAXF);
    const int base = grp * 128;
    int nf = cnt - base;
    if (nf <= 0) return;
    if (nf > 128) nf = 128;

    int* rows_s = reinterpret_cast<int*>(smem + R_ROWS);
    int* labs_s = reinterpret_cast<int*>(smem + R_LABS);
    if (tid < 128) {
        const int code = g_flags1[d * MAXF + base + ((tid < nf) ? tid : 0)];
        rows_s[tid] = code >> 1;
    }
    __syncthreads();
    if (tid < 128) labs_s[tid] = g_labels[d * NB + rows_s[tid]];

    // gather A hi+lo rows into swizzled smem
#pragma unroll
    for (int it = 0; it < 8; ++it) {
        const int c = it * NTHREADS + tid;       // 0..4095
        const int comp = c >> 11;
        const int rem = c & 2047;
        const int f = rem >> 4, kc = rem & 15;
        const int row = rows_s[f];
        const __half* src = (comp ? g_lo : g_hi)
            + ((size_t)d * NB + row) * NF + kc * 8;
        const uint4 v = *reinterpret_cast<const uint4*>(src);
        const uint32_t dstb = (uint32_t)f * 256u
            + (((uint32_t)kc * 16u) ^ (((uint32_t)f & 7u) << 4));
        *reinterpret_cast<uint4*>(smem + (comp ? R_AL : R_AH) + dstb) = v;
    }

    const __half* __restrict__ gh = g_hi + (size_t)d * NB * NF;
    const __half* __restrict__ gl = g_lo + (size_t)d * NB * NF;
    const int* __restrict__ labd = g_labels + d * NB;

    const int t0 = slice * (NT / NSLICE);
    copy_tile_async(sb + R_B, gh + (size_t)t0 * BN * NF, tid);
    copy_tile_async(sb + R_B + 32768u, gl + (size_t)t0 * BN * NF, tid);
    CP_COMMIT();

    const uint32_t cxA = ((uint32_t)(L >> 4) * 16u) ^ (((uint32_t)L & 7u) << 4);
    const uint32_t cxB = ((uint32_t)((L >> 3) & 1) * 16u) ^ (((uint32_t)L & 7u) << 4);
    uint32_t aBase[2];
#pragma unroll
    for (int mt = 0; mt < 2; ++mt) {
        const int rowA = wm * 32 + mt * 16 + (L & 7) + ((L >> 3) & 1) * 8;
        aBase[mt] = sb + R_AH + (uint32_t)rowA * 256u;
    }
    uint32_t bRow[2];
#pragma unroll
    for (int bi = 0; bi < 2; ++bi) {
        const int rowB = wn * 32 + bi * 16 + (L & 7) + (L >> 4) * 8;
        bRow[bi] = (uint32_t)rowB * 256u;
    }

    const int rbase = wm * 32 + (L >> 2);
    int li[4], rid[4];
#pragma unroll
    for (int s = 0; s < 4; ++s) {
        const int f = rbase + (s & 1) * 8 + (s >> 1) * 16;
        li[s] = labs_s[f];
        rid[s] = rows_s[f];
    }
    __syncthreads();   // A gather + meta visible before ldsm

    const float INF = __int_as_float(0x7f800000);
    float p1[4], p2[4], n1[4], n2[4];
    int i1[4], j1[4];
#pragma unroll
    for (int s = 0; s < 4; ++s) {
        p1[s] = INF; p2[s] = INF; n1[s] = -INF; n2[s] = -INF;
        i1[s] = -1; j1[s] = -1;
    }

    for (int tt = 0; tt < NT / NSLICE; ++tt) {
        const int t = t0 + tt;
        if (tt + 1 < NT / NSLICE) {
            const uint32_t bo = R_B + (uint32_t)((tt + 1) & 1) * 65536u;
            copy_tile_async(sb + bo, gh + (size_t)(t + 1) * BN * NF, tid);
            copy_tile_async(sb + bo + 32768u, gl + (size_t)(t + 1) * BN * NF, tid);
            CP_COMMIT();
            CP_WAIT1();
        } else {
            CP_WAIT0();
        }
        __syncthreads();

        const int jb = t * BN + wn * 32 + (L & 3) * 2;
        int labc[4][2];
#pragma unroll
        for (int nt = 0; nt < 4; ++nt) {
            const int2 lv = *reinterpret_cast<const int2*>(labd + jb + nt * 8);
            labc[nt][0] = lv.x; labc[nt][1] = lv.y;
        }

        float acc[2][4][4];
#pragma unroll
        for (int mt = 0; mt < 2; ++mt)
#pragma unroll
            for (int nt = 0; nt < 4; ++nt)
#pragma unroll
                for (int r = 0; r < 4; ++r) acc[mt][nt][r] = 0.0f;

        const uint32_t sbB = sb + R_B + (uint32_t)(tt & 1) * 65536u;
#pragma unroll
        for (int ks = 0; ks < 8; ++ks) {
            const uint32_t offA = ((uint32_t)ks * 32u) ^ cxA;
            const uint32_t offB = ((uint32_t)ks * 32u) ^ cxB;
            uint32_t Ah[2][4], Al[2][4], Bh[2][4], Bl[2][4];
            ldsm4(Ah[0], aBase[0] + offA);
            ldsm4(Ah[1], aBase[1] + offA);
            ldsm4(Bh[0], sbB + bRow[0] + offB);
            ldsm4(Bh[1], sbB + bRow[1] + offB);
            ldsm4(Al[0], aBase[0] + 32768u + offA);
            ldsm4(Al[1], aBase[1] + 32768u + offA);
            ldsm4(Bl[0], sbB + 32768u + bRow[0] + offB);
            ldsm4(Bl[1], sbB + 32768u + bRow[1] + offB);
#pragma unroll
            for (int bi = 0; bi < 2; ++bi)
#pragma unroll
                for (int mt = 0; mt < 2; ++mt) {
                    mma16816(acc[mt][2 * bi],     Ah[mt], Bh[bi]);
                    mma16816(acc[mt][2 * bi + 1], Ah[mt], Bh[bi] + 2);
                }
#pragma unroll
            for (int bi = 0; bi < 2; ++bi)
#pragma unroll
                for (int mt = 0; mt < 2; ++mt) {
                    mma16816(acc[mt][2 * bi],     Al[mt], Bh[bi]);
                    mma16816(acc[mt][2 * bi + 1], Al[mt], Bh[bi] + 2);
                }
#pragma unroll
            for (int bi = 0; bi < 2; ++bi)
#pragma unroll
                for (int mt = 0; mt < 2; ++mt) {
                    mma16816(acc[mt][2 * bi],     Ah[mt], Bl[bi]);
                    mma16816(acc[mt][2 * bi + 1], Ah[mt], Bl[bi] + 2);
                }
        }

#pragma unroll
        for (int nt = 0; nt < 4; ++nt)
#pragma unroll
            for (int e = 0; e < 2; ++e) {
                const int lj = labc[nt][e];
                const int j = jb + nt * 8 + e;
#pragma unroll
                for (int s = 0; s < 4; ++s) {
                    const float v = acc[s >> 1][nt][(s & 1) * 2 + e];
                    if (lj == li[s]) {
                        if (j != rid[s]) {
                            if (v < p1[s]) { p2[s] = p1[s]; p1[s] = v; i1[s] = j; }
                            else if (v < p2[s]) p2[s] = v;
                        }
                    } else {
                        if (v > n1[s]) { n2[s] = n1[s]; n1[s] = v; j1[s] = j; }
                        else if (v > n2[s]) n2[s] = v;
                    }
                }
            }
        __syncthreads();
    }

#pragma unroll
    for (int s = 0; s < 4; ++s) {
#pragma unroll
        for (int off = 1; off <= 2; off <<= 1) {
            const float q1 = __shfl_xor_sync(~0u, p1[s], off);
            const float q2 = __shfl_xor_sync(~0u, p2[s], off);
            const int   qi = __shfl_xor_sync(~0u, i1[s], off);
            const float m1 = __shfl_xor_sync(~0u, n1[s], off);
            const float m2 = __shfl_xor_sync(~0u, n2[s], off);
            const int   mi = __shfl_xor_sync(~0u, j1[s], off);
            MERGE_MIN(p1[s], p2[s], i1[s], q1, q2, qi);
            MERGE_MAX(n1[s], n2[s], j1[s], m1, m2, mi);
        }
    }

    float* scr = reinterpret_cast<float*>(smem + R_SCR);
    if (wn > 0 && (L & 3) == 0) {
#pragma unroll
        for (int s = 0; s < 4; ++s) {
            const int f = rbase + (s & 1) * 8 + (s >> 1) * 16;
            float* sr = scr + (f * 4 + wn) * 8;
            sr[0] = p1[s]; sr[1] = p2[s];
            reinterpret_cast<int*>(sr)[2] = i1[s];
            sr[3] = n1[s]; sr[4] = n2[s];
            reinterpret_cast<int*>(sr)[5] = j1[s];
        }
    }
    __syncthreads();
    if (wn == 0 && (L & 3) == 0) {
#pragma unroll
        for (int s = 0; s < 4; ++s) {
            const int f = rbase + (s & 1) * 8 + (s >> 1) * 16;
            float P1 = p1[s], P2 = p2[s], N1 = n1[s], N2 = n2[s];
            int I1 = i1[s], J1 = j1[s];
#pragma unroll
            for (int o = 1; o < 4; ++o) {
                const float* sr = scr + (f * 4 + o) * 8;
                MERGE_MIN(P1, P2, I1, sr[0], sr[1], reinterpret_cast<const int*>(sr)[2]);
                MERGE_MAX(N1, N2, J1, sr[3], sr[4], reinterpret_cast<const int*>(sr)[5]);
            }
            if (f < nf) {
                float4* dst = reinterpret_cast<float4*>(
                    g_rp + (((size_t)d * MAXF + base + f) * NSLICE + slice) * 8);
                dst[0] = make_float4(P1, P2, __int_as_float(I1), N1);
                dst[1] = make_float4(N2, __int_as_float(J1), 0.f, 0.f);
            }
        }
    }
}

// ---------------- L2 merge: fold slices, write outputs, cascade to L3 ----------------
__global__ void refine2_merge(const float* __restrict__ emb,
                              float* __restrict__ pos_dist,
                              float* __restrict__ neg_dist,
                              float* __restrict__ pos_embed,
                              float* __restrict__ neg_embed) {
    const int wid = threadIdx.x >> 5, L = threadIdx.x & 31;
    const int d = blockIdx.y;
    const int x = blockIdx.x * 8 + wid;
    const int cnt = min(g_fcnt[d], MAXF);
    if (x >= cnt) return;
    const int code = g_flags1[d * MAXF + x];
    const int row = code >> 1, side = code & 1;

    const float4* bp = reinterpret_cast<const float4*>(
        g_rp + (((size_t)d * MAXF + x) * NSLICE + (L & 7)) * 8);
    const float4 a = bp[0], b = bp[1];
    float P1 = a.x, P2 = a.y, N1 = a.w, N2 = b.x;
    int I1 = __float_as_int(a.z), J1 = __float_as_int(b.y);
#pragma unroll
    for (int off = 1; off <= 4; off <<= 1) {
        const float q1 = __shfl_xor_sync(~0u, P1, off);
        const float q2 = __shfl_xor_sync(~0u, P2, off);
        const int   qi = __shfl_xor_sync(~0u, I1, off);
        const float m1 = __shfl_xor_sync(~0u, N1, off);
        const float m2 = __shfl_xor_sync(~0u, N2, off);
        const int   mi = __shfl_xor_sync(~0u, J1, off);
        MERGE_MIN(P1, P2, I1, q1, q2, qi);
        MERGE_MAX(N1, N2, J1, m1, m2, mi);
    }
    float v1 = side ? N1 : P1;
    float gap = side ? (N1 - N2) : (P2 - P1);
    int idx = side ? J1 : I1;
    v1  = __shfl_sync(~0u, v1, 0);
    gap = __shfl_sync(~0u, gap, 0);
    idx = __shfl_sync(~0u, idx, 0);
    if (idx < 0) return;

    const size_t go = (size_t)d * NB + row;
    if (L == 0) {
        (side ? neg_dist : pos_dist)[go] = v1;
        if (gap < MARGIN2) {
            const int y = atomicAdd(&g_fcnt3, 1);
            if (y < MAXF3) g_flags3[y] = (int)((go << 1) | (size_t)side);
        }
    }
    float4* dst = reinterpret_cast<float4*>(
        (side ? neg_embed : pos_embed) + go * NF);
    dst[L] = reinterpret_cast<const float4*>(
        emb + ((size_t)d * NB + idx) * NF)[L];
}

// ---------------- L3: exact fp32 full-row rescan (rare) ----------------
__global__ void refine3_scan(const float* __restrict__ emb) {
    __shared__ float srow[NF];
    __shared__ int sli;
    __shared__ unsigned long long swb[8];
    const int cnt = min(g_fcnt3, MAXF3);
    for (int f = blockIdx.x; f < cnt; f += gridDim.x) {
        const int code = g_flags3[f];
        const int side = code & 1, gr = code >> 1;
        const int d = gr >> 13, row = gr & (NB - 1);
        const float* __restrict__ embd = emb + (size_t)d * NB * NF;
        __syncthreads();
        if (threadIdx.x < NF) srow[threadIdx.x] = embd[(size_t)row * NF + threadIdx.x];
        if (threadIdx.x == 0) sli = g_labels[d * NB + row];
        __syncthreads();
        const int li = sli;
        const float4* a4 = reinterpret_cast<const float4*>(srow);

        unsigned long long best = 0ull;
        for (int j = threadIdx.x; j < NB; j += blockDim.x) {
            const int lj = g_labels[d * NB + j];
            const bool valid = side ? (lj != li) : (lj == li && j != row);
            if (!valid) continue;
            const float4* b4 = reinterpret_cast<const float4*>(embd + (size_t)j * NF);
            float accv = 0.0f;
#pragma unroll
            for (int qq = 0; qq < 32; ++qq) {
                const float4 av = a4[qq], bv = b4[qq];
                accv = fmaf(av.x, bv.x, accv);
                accv = fmaf(av.y, bv.y, accv);
                accv = fmaf(av.z, bv.z, accv);
                accv = fmaf(av.w, bv.w, accv);
            }
            uint32_t key = fkey(accv);
            if (!side) key = ~key;
            const unsigned long long pk =
                ((unsigned long long)key << 32) | (uint32_t)(NB - 1 - j);
            if (pk > best) best = pk;
        }
#pragma unroll
        for (int off = 16; off > 0; off >>= 1) {
            const unsigned long long o = __shfl_xor_sync(~0u, best, off);
            if (o > best) best = o;
        }
        if ((threadIdx.x & 31) == 0) swb[threadIdx.x >> 5] = best;
        __syncthreads();
        if (threadIdx.x == 0) {
            unsigned long long b = swb[0];
#pragma unroll
            for (int o = 1; o < 8; ++o) if (swb[o] > b) b = swb[o];
            g_best[f] = b;
        }
    }
}

__global__ void refine3_write(const float* __restrict__ emb,
                              float* __restrict__ pos_dist,
                              float* __restrict__ neg_dist,
                              float* __restrict__ pos_embed,
                              float* __restrict__ neg_embed) {
    const int cnt = min(g_fcnt3, MAXF3);
    for (int f = blockIdx.x; f < cnt; f += gridDim.x) {
        const int code = g_flags3[f];
        const int side = code & 1, gr = code >> 1;
        const int d = gr >> 13, row = gr & (NB - 1);
        const unsigned long long pk = g_best[f];
        if (pk == 0ull) continue;
        const uint32_t key = (uint32_t)(pk >> 32);
        const int j = NB - 1 - (int)(pk & 0xFFFFFFFFull);
        const uint32_t m = side ? key : ~key;
        const uint32_t u = (m & 0x80000000u) ? (m & 0x7FFFFFFFu) : ~m;
        const float v = __uint_as_float(u);

        const size_t go = (size_t)d * NB + row;
        float* dist = side ? neg_dist : pos_dist;
        float* embo = side ? neg_embed : pos_embed;
        if (threadIdx.x == 0) dist[go] = v;
        embo[go * NF + threadIdx.x] = emb[((size_t)d * NB + j) * NF + threadIdx.x];
    }
}

// ---------------- launch ----------------
extern "C" void kernel_launch(void* const* d_in, const int* in_sizes, int n_in,
                              void* d_out, int out_size) {
    (void)in_sizes; (void)n_in; (void)out_size;
    const float* emb = (const float*)d_in[0];
    const unsigned int* labw = (const unsigned int*)d_in[1];

    float* out = (float*)d_out;
    float* pos_dist  = out;
    float* neg_dist  = out + (size_t)NDOM * NB;
    float* pos_embed = out + (size_t)2 * NDOM * NB;
    float* neg_embed = pos_embed + (size_t)NDOM * NB * NF;

    convert_labels_kernel<<<1, 256>>>(labw, NDOM * NB);
    split_kernel<<<(NDOM * NB * NF / 4) / 256, 256>>>(emb);

    cudaFuncSetAttribute(mine_kernel,
                         cudaFuncAttributeMaxDynamicSharedMemorySize, SMEM_BYTES);
    dim3 grid(NB / BM, NDOM);
    mine_kernel<<<grid, NTHREADS, SMEM_BYTES>>>(emb, pos_dist, neg_dist,
                                                pos_embed, neg_embed);

    cudaFuncSetAttribute(refine2_kernel,
                         cudaFuncAttributeMaxDynamicSharedMemorySize, SMEM2_BYTES);
    dim3 rgrid(MAXF / 128, NSLICE, NDOM);
    refine2_kernel<<<rgrid, NTHREADS, SMEM2_BYTES>>>();

    dim3 mgrid(MAXF / 8, NDOM);
    refine2_merge<<<mgrid, 256>>>(emb, pos_dist, neg_dist, pos_embed, neg_embed);

    refine3_scan<<<128, 256>>>(emb);
    refine3_write<<<64, NF>>>(emb, pos_dist, neg_dist, pos_embed, neg_embed);
}

// round 11
// speedup vs baseline: 1.9863x; 1.0195x over previous
#include <cuda_runtime.h>
#include <cuda_fp16.h>
#include <cstdint>

#define NDOM 4
#define NB   8192
#define NF   128
#define BM   128
#define BN   128
#define NT   (NB / BN)
#define NTHREADS 512
#define MARGIN1 0.022f
#define MARGIN2 2e-4f
#define MAXF  4096
#define MAXF3 2048
#define NSLICE 8
#define DOMBYTES 2097152u      /* NB*NF*2 bytes per domain */
#define TILEBYTES 32768u

// ---------------- SMEM layouts ----------------
// mine kernel
#define OFF_A   0u
#define OFF_B   32768u         /* 2 x 32KB */
#define OFF_SCR 98304u         /* 16KB */
#define OFF_MB  114688u        /* 3 mbarriers: A, buf0, buf1 */
#define SMEM_BYTES 114720u
// refine2 kernel
#define R_AH   0u
#define R_AL   32768u
#define R_B    65536u          /* 2 x 64KB (hi, lo at +32768) */
#define R_SCR  196608u
#define R_ROWS 212992u
#define R_LABS 213504u
#define R_MB   214016u         /* 2 mbarriers */
#define SMEM2_BYTES 214032u

__device__ int g_labels[NDOM * NB];
__device__ int g_fcnt[NDOM];
__device__ int g_flags1[NDOM * MAXF];
__device__ int g_fcnt3;
__device__ int g_flags3[MAXF3];
__device__ unsigned long long g_best[MAXF3];
// tile-swizzled fp16 layouts: domain d, tile T, row rr, 16B-chunk kc at
// byte d*DOMBYTES + T*32768 + rr*256 + ((kc*16) ^ ((rr&7)<<4))
__device__ __half g_hi[NDOM * NB * NF];
__device__ __half g_lo[NDOM * NB * NF];
__device__ float g_rp[(size_t)NDOM * MAXF * NSLICE * 8];

// ---------------- helpers ----------------
__device__ __forceinline__ uint32_t smem_u32(const void* p) {
    uint32_t a;
    asm("{ .reg .u64 t; cvta.to.shared.u64 t, %1; cvt.u32.u64 %0, t; }"
        : "=r"(a) : "l"(p));
    return a;
}
__device__ __forceinline__ uint32_t fkey(float v) {
    uint32_t u = __float_as_uint(v);
    return (u & 0x80000000u) ? ~u : (u | 0x80000000u);
}
__device__ __forceinline__ void ldsm4(uint32_t* r, uint32_t addr) {
    asm volatile("ldmatrix.sync.aligned.m8n8.x4.shared.b16 {%0,%1,%2,%3}, [%4];"
                 : "=r"(r[0]), "=r"(r[1]), "=r"(r[2]), "=r"(r[3]) : "r"(addr));
}
__device__ __forceinline__ void mma16816(float* d, const uint32_t* a,
                                         const uint32_t* b) {
    asm volatile(
        "mma.sync.aligned.m16n8k16.row.col.f32.f16.f16.f32 "
        "{%0,%1,%2,%3}, {%4,%5,%6,%7}, {%8,%9}, {%0,%1,%2,%3};"
        : "+f"(d[0]), "+f"(d[1]), "+f"(d[2]), "+f"(d[3])
        : "r"(a[0]), "r"(a[1]), "r"(a[2]), "r"(a[3]), "r"(b[0]), "r"(b[1]));
}

#define MBAR_INIT(mb, c) \
    asm volatile("mbarrier.init.shared.b64 [%0], %1;" :: "r"(mb), "r"(c) : "memory")
#define MBAR_EXPECT(mb, tx) \
    asm volatile("mbarrier.arrive.expect_tx.shared.b64 _, [%0], %1;" :: "r"(mb), "r"(tx) : "memory")
#define BULK_G2S(dst, src, size, mb) \
    asm volatile("cp.async.bulk.shared::cluster.global.mbarrier::complete_tx::bytes [%0], [%1], %2, [%3];" \
                 :: "r"(dst), "l"(src), "r"(size), "r"(mb) : "memory")
#define FENCE_ASYNC() asm volatile("fence.proxy.async.shared::cta;" ::: "memory")
#define MBAR_WAIT(mb, ph) do {                                                          \
    uint32_t _done;                                                                     \
    asm volatile("{ .reg .pred p; mbarrier.try_wait.parity.acquire.cta.shared::cta.b64 p, [%1], %2; selp.b32 %0, 1, 0, p; }" \
                 : "=r"(_done) : "r"(mb), "r"((uint32_t)(ph)) : "memory");              \
    while (!_done) {                                                                    \
        asm volatile("{ .reg .pred p; mbarrier.try_wait.parity.acquire.cta.shared::cta.b64 p, [%1], %2, 0x989680; selp.b32 %0, 1, 0, p; }" \
                     : "=r"(_done) : "r"(mb), "r"((uint32_t)(ph)) : "memory");          \
    }                                                                                   \
} while (0)

#define MERGE_MIN(P1, P2, I1, q1, q2, qi) \
    do { if ((q1) < (P1)) { P2 = fminf(P1, q2); P1 = q1; I1 = qi; } \
         else { P2 = fminf(P2, q1); } } while (0)
#define MERGE_MAX(N1, N2, J1, m1, m2, mi) \
    do { if ((m1) > (N1)) { N2 = fmaxf(N1, m2); N1 = m1; J1 = mi; } \
         else { N2 = fmaxf(N2, m1); } } while (0)

// ---------------- one-shot fp32 -> tile-swizzled fp16 hi/lo ----------------
__global__ void split_kernel(const float* __restrict__ emb) {
    const int i = blockIdx.x * blockDim.x + threadIdx.x;   // float4 index
    const float4 v = reinterpret_cast<const float4*>(emb)[i];
    const __half hx = __float2half_rn(v.x), hy = __float2half_rn(v.y);
    const __half hz = __float2half_rn(v.z), hw = __float2half_rn(v.w);
    const __half lx = __float2half_rn(v.x - __half2float(hx));
    const __half ly = __float2half_rn(v.y - __half2float(hy));
    const __half lz = __float2half_rn(v.z - __half2float(hz));
    const __half lw = __float2half_rn(v.w - __half2float(hw));
    uint2 hv, lv;
    hv.x = ((uint32_t)__half_as_ushort(hx)) | ((uint32_t)__half_as_ushort(hy) << 16);
    hv.y = ((uint32_t)__half_as_ushort(hz)) | ((uint32_t)__half_as_ushort(hw) << 16);
    lv.x = ((uint32_t)__half_as_ushort(lx)) | ((uint32_t)__half_as_ushort(ly) << 16);
    lv.y = ((uint32_t)__half_as_ushort(lz)) | ((uint32_t)__half_as_ushort(lw) << 16);

    const int r = i >> 5;              // global row (d*NB + rd)
    const int k0 = (i & 31) * 4;
    const int rr = r & 127;
    const size_t gbyte = (size_t)(r >> 7) * TILEBYTES + (size_t)rr * 256u
        + ((((uint32_t)(k0 >> 3) << 4) ^ (((uint32_t)rr & 7u) << 4))
           + (((uint32_t)k0 & 7u) << 1));
    *reinterpret_cast<uint2*>(reinterpret_cast<char*>(g_hi) + gbyte) = hv;
    *reinterpret_cast<uint2*>(reinterpret_cast<char*>(g_lo) + gbyte) = lv;
}

// ---------------- label normalization + counters reset ----------------
__global__ void convert_labels_kernel(const unsigned int* __restrict__ w, int n) {
    __shared__ int s_any;
    if (threadIdx.x == 0) { s_any = 0; g_fcnt3 = 0; }
    if (threadIdx.x < NDOM) g_fcnt[threadIdx.x] = 0;
    __syncthreads();
    int any = 0;
    for (int i = threadIdx.x; i < n / 2; i += blockDim.x)
        any |= (w[2 * i + 1] != 0u);
    if (any) atomicOr(&s_any, 1);
    for (int i = threadIdx.x; i < MAXF3; i += blockDim.x) g_best[i] = 0ull;
    __syncthreads();
    const bool is64 = (s_any == 0);
    for (int i = threadIdx.x; i < n; i += blockDim.x)
        g_labels[i] = is64 ? (int)w[2 * i] : (int)w[i];
}

// ---------------- L1: fused single-pass HMMA GEMM + top-2 mining ----------------
__global__ __launch_bounds__(NTHREADS, 1)
void mine_kernel(const float* __restrict__ emb,
                 float* __restrict__ pos_dist, float* __restrict__ neg_dist,
                 float* __restrict__ pos_embed, float* __restrict__ neg_embed) {
    extern __shared__ char smem[];
    const uint32_t sb = smem_u32(smem);
    const int tid = threadIdx.x;
    const int w = tid >> 5, L = tid & 31;
    const int wm = w & 3, wn = w >> 2;
    const int d = blockIdx.y;
    const int tb = blockIdx.x * BM;

    const float* __restrict__ embd = emb + (size_t)d * NB * NF;
    const char* __restrict__ gtiles =
        reinterpret_cast<const char*>(g_hi) + (size_t)d * DOMBYTES;
    const int* __restrict__ labd = g_labels + d * NB;

    const uint32_t barA = sb + OFF_MB;
    const uint32_t bar0 = sb + OFF_MB + 8;
    if (tid == 0) { MBAR_INIT(barA, 1); MBAR_INIT(bar0, 1); MBAR_INIT(bar0 + 8, 1); }
    FENCE_ASYNC();
    __syncthreads();
    if (tid == 0) {
        MBAR_EXPECT(barA, TILEBYTES);
        BULK_G2S(sb + OFF_A, gtiles + (size_t)blockIdx.x * TILEBYTES, TILEBYTES, barA);
        MBAR_EXPECT(bar0, TILEBYTES);
        BULK_G2S(sb + OFF_B, gtiles, TILEBYTES, bar0);
    }

    const uint32_t cxA = ((uint32_t)(L >> 4) * 16u) ^ (((uint32_t)L & 7u) << 4);
    const uint32_t cxB = ((uint32_t)((L >> 3) & 1) * 16u) ^ (((uint32_t)L & 7u) << 4);
    uint32_t aBase[2];
#pragma unroll
    for (int mt = 0; mt < 2; ++mt) {
        const int rowA = wm * 32 + mt * 16 + (L & 7) + ((L >> 3) & 1) * 8;
        aBase[mt] = sb + OFF_A + (uint32_t)rowA * 256u;
    }
    uint32_t bRow[2];
#pragma unroll
    for (int bi = 0; bi < 2; ++bi) {
        const int rowB = wn * 32 + bi * 16 + (L & 7) + (L >> 4) * 8;
        bRow[bi] = (uint32_t)rowB * 256u;
    }

    const int rbase = wm * 32 + (L >> 2);
    int li[4];
#pragma unroll
    for (int s = 0; s < 4; ++s)
        li[s] = labd[tb + rbase + (s & 1) * 8 + (s >> 1) * 16];

    const float INF = __int_as_float(0x7f800000);
    float p1[4], p2[4], n1[4], n2[4];
    int i1[4], j1[4];
#pragma unroll
    for (int s = 0; s < 4; ++s) {
        p1[s] = INF; p2[s] = INF; n1[s] = -INF; n2[s] = -INF;
        i1[s] = -1; j1[s] = -1;
    }

    MBAR_WAIT(barA, 0);

    for (int t = 0; t < NT; ++t) {
        // issue t+1 into the other buffer (its readers finished at end of t-1)
        if (t + 1 < NT && tid == 0) {
            const uint32_t bn_ = bar0 + (uint32_t)((t + 1) & 1) * 8u;
            MBAR_EXPECT(bn_, TILEBYTES);
            BULK_G2S(sb + OFF_B + (uint32_t)((t + 1) & 1) * TILEBYTES,
                     gtiles + (size_t)(t + 1) * TILEBYTES, TILEBYTES, bn_);
        }
        MBAR_WAIT(bar0 + (uint32_t)(t & 1) * 8u, (t >> 1) & 1);

        const int jb = t * BN + wn * 32 + (L & 3) * 2;
        int labc[4][2];
#pragma unroll
        for (int nt = 0; nt < 4; ++nt) {
            const int2 lv = *reinterpret_cast<const int2*>(labd + jb + nt * 8);
            labc[nt][0] = lv.x; labc[nt][1] = lv.y;
        }

        float acc[2][4][4];
#pragma unroll
        for (int mt = 0; mt < 2; ++mt)
#pragma unroll
            for (int nt = 0; nt < 4; ++nt)
#pragma unroll
                for (int r = 0; r < 4; ++r) acc[mt][nt][r] = 0.0f;

        const uint32_t sbB = sb + OFF_B + (uint32_t)(t & 1) * TILEBYTES;
#pragma unroll
        for (int ks = 0; ks < 8; ++ks) {
            const uint32_t offA = ((uint32_t)ks * 32u) ^ cxA;
            const uint32_t offB = ((uint32_t)ks * 32u) ^ cxB;
            uint32_t A[2][4], B[2][4];
            ldsm4(A[0], aBase[0] + offA);
            ldsm4(A[1], aBase[1] + offA);
            ldsm4(B[0], sbB + bRow[0] + offB);
            ldsm4(B[1], sbB + bRow[1] + offB);
#pragma unroll
            for (int bi = 0; bi < 2; ++bi)
#pragma unroll
                for (int mt = 0; mt < 2; ++mt) {
                    mma16816(acc[mt][2 * bi],     A[mt], B[bi]);
                    mma16816(acc[mt][2 * bi + 1], A[mt], B[bi] + 2);
                }
        }

#pragma unroll
        for (int nt = 0; nt < 4; ++nt)
#pragma unroll
            for (int e = 0; e < 2; ++e) {
                const int lj = labc[nt][e];
                const int j = jb + nt * 8 + e;
#pragma unroll
                for (int s = 0; s < 4; ++s) {
                    const float v = acc[s >> 1][nt][(s & 1) * 2 + e];
                    if (lj == li[s]) {
                        const int growr = tb + rbase + (s & 1) * 8 + (s >> 1) * 16;
                        if (j != growr) {
                            if (v < p1[s]) { p2[s] = p1[s]; p1[s] = v; i1[s] = j; }
                            else if (v < p2[s]) p2[s] = v;
                        }
                    } else {
                        if (v > n1[s]) { n2[s] = n1[s]; n1[s] = v; j1[s] = j; }
                        else if (v > n2[s]) n2[s] = v;
                    }
                }
            }
        __syncthreads();   // all warps done reading buf t&1 before its reuse
    }

#pragma unroll
    for (int s = 0; s < 4; ++s) {
#pragma unroll
        for (int off = 1; off <= 2; off <<= 1) {
            const float q1 = __shfl_xor_sync(~0u, p1[s], off);
            const float q2 = __shfl_xor_sync(~0u, p2[s], off);
            const int   qi = __shfl_xor_sync(~0u, i1[s], off);
            const float m1 = __shfl_xor_sync(~0u, n1[s], off);
            const float m2 = __shfl_xor_sync(~0u, n2[s], off);
            const int   mi = __shfl_xor_sync(~0u, j1[s], off);
            MERGE_MIN(p1[s], p2[s], i1[s], q1, q2, qi);
            MERGE_MAX(n1[s], n2[s], j1[s], m1, m2, mi);
        }
    }

    float* scr = reinterpret_cast<float*>(smem + OFF_SCR);
    if (wn > 0 && (L & 3) == 0) {
#pragma unroll
        for (int s = 0; s < 4; ++s) {
            const int row = rbase + (s & 1) * 8 + (s >> 1) * 16;
            float* sr = scr + (row * 4 + wn) * 8;
            sr[0] = p1[s]; sr[1] = p2[s];
            reinterpret_cast<int*>(sr)[2] = i1[s];
            sr[3] = n1[s]; sr[4] = n2[s];
            reinterpret_cast<int*>(sr)[5] = j1[s];
        }
    }
    __syncthreads();
    if (wn == 0 && (L & 3) == 0) {
#pragma unroll
        for (int s = 0; s < 4; ++s) {
            const int row = rbase + (s & 1) * 8 + (s >> 1) * 16;
            float P1 = p1[s], P2 = p2[s], N1 = n1[s], N2 = n2[s];
            int I1 = i1[s], J1 = j1[s];
#pragma unroll
            for (int o = 1; o < 4; ++o) {
                const float* sr = scr + (row * 4 + o) * 8;
                MERGE_MIN(P1, P2, I1, sr[0], sr[1], reinterpret_cast<const int*>(sr)[2]);
                MERGE_MAX(N1, N2, J1, sr[3], sr[4], reinterpret_cast<const int*>(sr)[5]);
            }
            const bool has_pos = (P1 < INF);
            const size_t go = (size_t)d * NB + tb + row;
            pos_dist[go] = has_pos ? P1 : 0.0f;
            neg_dist[go] = has_pos ? N1 : 0.0f;
            reinterpret_cast<int*>(scr)[(row * 4) * 8 + 6] = has_pos ? I1 : -1;
            reinterpret_cast<int*>(scr)[(row * 4) * 8 + 7] = has_pos ? J1 : -1;
            if (has_pos) {
                const int code = (tb + row) << 1;
                if (P2 - P1 < MARGIN1) {
                    const int x = atomicAdd(&g_fcnt[d], 1);
                    if (x < MAXF) g_flags1[d * MAXF + x] = code | 0;
                }
                if (N1 - N2 < MARGIN1) {
                    const int x = atomicAdd(&g_fcnt[d], 1);
                    if (x < MAXF) g_flags1[d * MAXF + x] = code | 1;
                }
            }
        }
    }
    __syncthreads();

    for (int c = w; c < 256; c += 16) {
        const int row = c >> 1, side = c & 1;
        const int idx = reinterpret_cast<int*>(scr)[(row * 4) * 8 + 6 + side];
        float4* dst = reinterpret_cast<float4*>(
            (side ? neg_embed : pos_embed) + ((size_t)d * NB + tb + row) * NF);
        if (idx >= 0)
            dst[L] = reinterpret_cast<const float4*>(embd + (size_t)idx * NF)[L];
        else
            dst[L] = make_float4(0.f, 0.f, 0.f, 0.f);
    }
}

// ---------------- L2: batched 3-pass MMA refine over flagged rows ----------------
__global__ __launch_bounds__(NTHREADS, 1)
void refine2_kernel() {
    extern __shared__ char smem[];
    const uint32_t sb = smem_u32(smem);
    const int tid = threadIdx.x;
    const int w = tid >> 5, L = tid & 31;
    const int wm = w & 3, wn = w >> 2;
    const int d = blockIdx.z, grp = blockIdx.x, slice = blockIdx.y;

    const int cnt = min(g_fcnt[d], MAXF);
    const int base = grp * 128;
    int nf = cnt - base;
    if (nf <= 0) return;
    if (nf > 128) nf = 128;

    const char* __restrict__ ghT =
        reinterpret_cast<const char*>(g_hi) + (size_t)d * DOMBYTES;
    const char* __restrict__ glT =
        reinterpret_cast<const char*>(g_lo) + (size_t)d * DOMBYTES;
    const int* __restrict__ labd = g_labels + d * NB;

    const uint32_t bar0 = sb + R_MB;
    if (tid == 0) { MBAR_INIT(bar0, 1); MBAR_INIT(bar0 + 8, 1); }
    FENCE_ASYNC();
    __syncthreads();

    const int t0 = slice * (NT / NSLICE);
    if (tid == 0) {
        MBAR_EXPECT(bar0, 2 * TILEBYTES);
        BULK_G2S(sb + R_B, ghT + (size_t)t0 * TILEBYTES, TILEBYTES, bar0);
        BULK_G2S(sb + R_B + TILEBYTES, glT + (size_t)t0 * TILEBYTES, TILEBYTES, bar0);
    }

    int* rows_s = reinterpret_cast<int*>(smem + R_ROWS);
    int* labs_s = reinterpret_cast<int*>(smem + R_LABS);
    if (tid < 128) {
        const int code = g_flags1[d * MAXF + base + ((tid < nf) ? tid : 0)];
        rows_s[tid] = code >> 1;
    }
    __syncthreads();
    if (tid < 128) labs_s[tid] = labd[rows_s[tid]];

    // gather flagged A rows (hi+lo) from tile-swizzled gmem into swizzled smem
#pragma unroll
    for (int it = 0; it < 8; ++it) {
        const int c = it * NTHREADS + tid;       // 0..4095
        const int comp = c >> 11;
        const int rem = c & 2047;
        const int f = rem >> 4, kc = rem & 15;
        const int row = rows_s[f];
        const size_t srcb = (size_t)(row >> 7) * TILEBYTES + (size_t)(row & 127) * 256u
            + (((uint32_t)kc * 16u) ^ (((uint32_t)row & 7u) << 4));
        const uint4 v = *reinterpret_cast<const uint4*>((comp ? glT : ghT) + srcb);
        const uint32_t dstb = (uint32_t)f * 256u
            + (((uint32_t)kc * 16u) ^ (((uint32_t)f & 7u) << 4));
        *reinterpret_cast<uint4*>(smem + (comp ? R_AL : R_AH) + dstb) = v;
    }

    const uint32_t cxA = ((uint32_t)(L >> 4) * 16u) ^ (((uint32_t)L & 7u) << 4);
    const uint32_t cxB = ((uint32_t)((L >> 3) & 1) * 16u) ^ (((uint32_t)L & 7u) << 4);
    uint32_t aBase[2];
#pragma unroll
    for (int mt = 0; mt < 2; ++mt) {
        const int rowA = wm * 32 + mt * 16 + (L & 7) + ((L >> 3) & 1) * 8;
        aBase[mt] = sb + R_AH + (uint32_t)rowA * 256u;
    }
    uint32_t bRow[2];
#pragma unroll
    for (int bi = 0; bi < 2; ++bi) {
        const int rowB = wn * 32 + bi * 16 + (L & 7) + (L >> 4) * 8;
        bRow[bi] = (uint32_t)rowB * 256u;
    }

    const int rbase = wm * 32 + (L >> 2);
    int li[4], rid[4];
#pragma unroll
    for (int s = 0; s < 4; ++s) {
        const int f = rbase + (s & 1) * 8 + (s >> 1) * 16;
        li[s] = labs_s[f];
        rid[s] = rows_s[f];
    }
    __syncthreads();   // A gather + meta visible before ldsm

    const float INF = __int_as_float(0x7f800000);
    float p1[4], p2[4], n1[4], n2[4];
    int i1[4], j1[4];
#pragma unroll
    for (int s = 0; s < 4; ++s) {
        p1[s] = INF; p2[s] = INF; n1[s] = -INF; n2[s] = -INF;
        i1[s] = -1; j1[s] = -1;
    }

    for (int tt = 0; tt < NT / NSLICE; ++tt) {
        const int t = t0 + tt;
        if (tt + 1 < NT / NSLICE && tid == 0) {
            const uint32_t bn_ = bar0 + (uint32_t)((tt + 1) & 1) * 8u;
            const uint32_t bo = sb + R_B + (uint32_t)((tt + 1) & 1) * 65536u;
            MBAR_EXPECT(bn_, 2 * TILEBYTES);
            BULK_G2S(bo, ghT + (size_t)(t + 1) * TILEBYTES, TILEBYTES, bn_);
            BULK_G2S(bo + TILEBYTES, glT + (size_t)(t + 1) * TILEBYTES, TILEBYTES, bn_);
        }
        MBAR_WAIT(bar0 + (uint32_t)(tt & 1) * 8u, (tt >> 1) & 1);

        const int jb = t * BN + wn * 32 + (L & 3) * 2;
        int labc[4][2];
#pragma unroll
        for (int nt = 0; nt < 4; ++nt) {
            const int2 lv = *reinterpret_cast<const int2*>(labd + jb + nt * 8);
            labc[nt][0] = lv.x; labc[nt][1] = lv.y;
        }

        float acc[2][4][4];
#pragma unroll
        for (int mt = 0; mt < 2; ++mt)
#pragma unroll
            for (int nt = 0; nt < 4; ++nt)
#pragma unroll
                for (int r = 0; r < 4; ++r) acc[mt][nt][r] = 0.0f;

        const uint32_t sbB = sb + R_B + (uint32_t)(tt & 1) * 65536u;
#pragma unroll
        for (int ks = 0; ks < 8; ++ks) {
            const uint32_t offA = ((uint32_t)ks * 32u) ^ cxA;
            const uint32_t offB = ((uint32_t)ks * 32u) ^ cxB;
            uint32_t Ah[2][4], Al[2][4], Bh[2][4], Bl[2][4];
            ldsm4(Ah[0], aBase[0] + offA);
            ldsm4(Ah[1], aBase[1] + offA);
            ldsm4(Bh[0], sbB + bRow[0] + offB);
            ldsm4(Bh[1], sbB + bRow[1] + offB);
            ldsm4(Al[0], aBase[0] + 32768u + offA);
            ldsm4(Al[1], aBase[1] + 32768u + offA);
            ldsm4(Bl[0], sbB + TILEBYTES + bRow[0] + offB);
            ldsm4(Bl[1], sbB + TILEBYTES + bRow[1] + offB);
#pragma unroll
            for (int bi = 0; bi < 2; ++bi)
#pragma unroll
                for (int mt = 0; mt < 2; ++mt) {
                    mma16816(acc[mt][2 * bi],     Ah[mt], Bh[bi]);
                    mma16816(acc[mt][2 * bi + 1], Ah[mt], Bh[bi] + 2);
                }
#pragma unroll
            for (int bi = 0; bi < 2; ++bi)
#pragma unroll
                for (int mt = 0; mt < 2; ++mt) {
                    mma16816(acc[mt][2 * bi],     Al[mt], Bh[bi]);
                    mma16816(acc[mt][2 * bi + 1], Al[mt], Bh[bi] + 2);
                }
#pragma unroll
            for (int bi = 0; bi < 2; ++bi)
#pragma unroll
                for (int mt = 0; mt < 2; ++mt) {
                    mma16816(acc[mt][2 * bi],     Ah[mt], Bl[bi]);
                    mma16816(acc[mt][2 * bi + 1], Ah[mt], Bl[bi] + 2);
                }
        }

#pragma unroll
        for (int nt = 0; nt < 4; ++nt)
#pragma unroll
            for (int e = 0; e < 2; ++e) {
                const int lj = labc[nt][e];
                const int j = jb + nt * 8 + e;
#pragma unroll
                for (int s = 0; s < 4; ++s) {
                    const float v = acc[s >> 1][nt][(s & 1) * 2 + e];
                    if (lj == li[s]) {
                        if (j != rid[s]) {
                            if (v < p1[s]) { p2[s] = p1[s]; p1[s] = v; i1[s] = j; }
                            else if (v < p2[s]) p2[s] = v;
                        }
                    } else {
                        if (v > n1[s]) { n2[s] = n1[s]; n1[s] = v; j1[s] = j; }
                        else if (v > n2[s]) n2[s] = v;
                    }
                }
            }
        __syncthreads();
    }

#pragma unroll
    for (int s = 0; s < 4; ++s) {
#pragma unroll
        for (int off = 1; off <= 2; off <<= 1) {
            const float q1 = __shfl_xor_sync(~0u, p1[s], off);
            const float q2 = __shfl_xor_sync(~0u, p2[s], off);
            const int   qi = __shfl_xor_sync(~0u, i1[s], off);
            const float m1 = __shfl_xor_sync(~0u, n1[s], off);
            const float m2 = __shfl_xor_sync(~0u, n2[s], off);
            const int   mi = __shfl_xor_sync(~0u, j1[s], off);
            MERGE_MIN(p1[s], p2[s], i1[s], q1, q2, qi);
            MERGE_MAX(n1[s], n2[s], j1[s], m1, m2, mi);
        }
    }

    float* scr = reinterpret_cast<float*>(smem + R_SCR);
    if (wn > 0 && (L & 3) == 0) {
#pragma unroll
        for (int s = 0; s < 4; ++s) {
            const int f = rbase + (s & 1) * 8 + (s >> 1) * 16;
            float* sr = scr + (f * 4 + wn) * 8;
            sr[0] = p1[s]; sr[1] = p2[s];
            reinterpret_cast<int*>(sr)[2] = i1[s];
            sr[3] = n1[s]; sr[4] = n2[s];
            reinterpret_cast<int*>(sr)[5] = j1[s];
        }
    }
    __syncthreads();
    if (wn == 0 && (L & 3) == 0) {
#pragma unroll
        for (int s = 0; s < 4; ++s) {
            const int f = rbase + (s & 1) * 8 + (s >> 1) * 16;
            float P1 = p1[s], P2 = p2[s], N1 = n1[s], N2 = n2[s];
            int I1 = i1[s], J1 = j1[s];
#pragma unroll
            for (int o = 1; o < 4; ++o) {
                const float* sr = scr + (f * 4 + o) * 8;
                MERGE_MIN(P1, P2, I1, sr[0], sr[1], reinterpret_cast<const int*>(sr)[2]);
                MERGE_MAX(N1, N2, J1, sr[3], sr[4], reinterpret_cast<const int*>(sr)[5]);
            }
            if (f < nf) {
                float4* dst = reinterpret_cast<float4*>(
                    g_rp + (((size_t)d * MAXF + base + f) * NSLICE + slice) * 8);
                dst[0] = make_float4(P1, P2, __int_as_float(I1), N1);
                dst[1] = make_float4(N2, __int_as_float(J1), 0.f, 0.f);
            }
        }
    }
}

// ---------------- L2 merge: fold slices, write outputs, cascade to L3 ----------------
__global__ void refine2_merge(const float* __restrict__ emb,
                              float* __restrict__ pos_dist,
                              float* __restrict__ neg_dist,
                              float* __restrict__ pos_embed,
                              float* __restrict__ neg_embed) {
    const int wid = threadIdx.x >> 5, L = threadIdx.x & 31;
    const int d = blockIdx.y;
    const int x = blockIdx.x * 8 + wid;
    const int cnt = min(g_fcnt[d], MAXF);
    if (x >= cnt) return;
    const int code = g_flags1[d * MAXF + x];
    const int row = code >> 1, side = code & 1;

    const float4* bp = reinterpret_cast<const float4*>(
        g_rp + (((size_t)d * MAXF + x) * NSLICE + (L & 7)) * 8);
    const float4 a = bp[0], b = bp[1];
    float P1 = a.x, P2 = a.y, N1 = a.w, N2 = b.x;
    int I1 = __float_as_int(a.z), J1 = __float_as_int(b.y);
#pragma unroll
    for (int off = 1; off <= 4; off <<= 1) {
        const float q1 = __shfl_xor_sync(~0u, P1, off);
        const float q2 = __shfl_xor_sync(~0u, P2, off);
        const int   qi = __shfl_xor_sync(~0u, I1, off);
        const float m1 = __shfl_xor_sync(~0u, N1, off);
        const float m2 = __shfl_xor_sync(~0u, N2, off);
        const int   mi = __shfl_xor_sync(~0u, J1, off);
        MERGE_MIN(P1, P2, I1, q1, q2, qi);
        MERGE_MAX(N1, N2, J1, m1, m2, mi);
    }
    float v1 = side ? N1 : P1;
    float gap = side ? (N1 - N2) : (P2 - P1);
    int idx = side ? J1 : I1;
    v1  = __shfl_sync(~0u, v1, 0);
    gap = __shfl_sync(~0u, gap, 0);
    idx = __shfl_sync(~0u, idx, 0);
    if (idx < 0) return;

    const size_t go = (size_t)d * NB + row;
    if (L == 0) {
        (side ? neg_dist : pos_dist)[go] = v1;
        if (gap < MARGIN2) {
            const int y = atomicAdd(&g_fcnt3, 1);
            if (y < MAXF3) g_flags3[y] = (int)((go << 1) | (size_t)side);
        }
    }
    float4* dst = reinterpret_cast<float4*>(
        (side ? neg_embed : pos_embed) + go * NF);
    dst[L] = reinterpret_cast<const float4*>(
        emb + ((size_t)d * NB + idx) * NF)[L];
}

// ---------------- L3: exact fp32 full-row rescan (rare) ----------------
__global__ void refine3_scan(const float* __restrict__ emb) {
    __shared__ float srow[NF];
    __shared__ int sli;
    __shared__ unsigned long long swb[8];
    const int cnt = min(g_fcnt3, MAXF3);
    for (int f = blockIdx.x; f < cnt; f += gridDim.x) {
        const int code = g_flags3[f];
        const int side = code & 1, gr = code >> 1;
        const int d = gr >> 13, row = gr & (NB - 1);
        const float* __restrict__ embd = emb + (size_t)d * NB * NF;
        __syncthreads();
        if (threadIdx.x < NF) srow[threadIdx.x] = embd[(size_t)row * NF + threadIdx.x];
        if (threadIdx.x == 0) sli = g_labels[d * NB + row];
        __syncthreads();
        const int li = sli;
        const float4* a4 = reinterpret_cast<const float4*>(srow);

        unsigned long long best = 0ull;
        for (int j = threadIdx.x; j < NB; j += blockDim.x) {
            const int lj = g_labels[d * NB + j];
            const bool valid = side ? (lj != li) : (lj == li && j != row);
            if (!valid) continue;
            const float4* b4 = reinterpret_cast<const float4*>(embd + (size_t)j * NF);
            float accv = 0.0f;
#pragma unroll
            for (int qq = 0; qq < 32; ++qq) {
                const float4 av = a4[qq], bv = b4[qq];
                accv = fmaf(av.x, bv.x, accv);
                accv = fmaf(av.y, bv.y, accv);
                accv = fmaf(av.z, bv.z, accv);
                accv = fmaf(av.w, bv.w, accv);
            }
            uint32_t key = fkey(accv);
            if (!side) key = ~key;
            const unsigned long long pk =
                ((unsigned long long)key << 32) | (uint32_t)(NB - 1 - j);
            if (pk > best) best = pk;
        }
#pragma unroll
        for (int off = 16; off > 0; off >>= 1) {
            const unsigned long long o = __shfl_xor_sync(~0u, best, off);
            if (o > best) best = o;
        }
        if ((threadIdx.x & 31) == 0) swb[threadIdx.x >> 5] = best;
        __syncthreads();
        if (threadIdx.x == 0) {
            unsigned long long b = swb[0];
#pragma unroll
            for (int o = 1; o < 8; ++o) if (swb[o] > b) b = swb[o];
            g_best[f] = b;
        }
    }
}

__global__ void refine3_write(const float* __restrict__ emb,
                              float* __restrict__ pos_dist,
                              float* __restrict__ neg_dist,
                              float* __restrict__ pos_embed,
                              float* __restrict__ neg_embed) {
    const int cnt = min(g_fcnt3, MAXF3);
    for (int f = blockIdx.x; f < cnt; f += gridDim.x) {
        const int code = g_flags3[f];
        const int side = code & 1, gr = code >> 1;
        const int d = gr >> 13, row = gr & (NB - 1);
        const unsigned long long pk = g_best[f];
        if (pk == 0ull) continue;
        const uint32_t key = (uint32_t)(pk >> 32);
        const int j = NB - 1 - (int)(pk & 0xFFFFFFFFull);
        const uint32_t m = side ? key : ~key;
        const uint32_t u = (m & 0x80000000u) ? (m & 0x7FFFFFFFu) : ~m;
        const float v = __uint_as_float(u);

        const size_t go = (size_t)d * NB + row;
        float* dist = side ? neg_dist : pos_dist;
        float* embo = side ? neg_embed : pos_embed;
        if (threadIdx.x == 0) dist[go] = v;
        embo[go * NF + threadIdx.x] = emb[((size_t)d * NB + j) * NF + threadIdx.x];
    }
}

// ---------------- launch ----------------
extern "C" void kernel_launch(void* const* d_in, const int* in_sizes, int n_in,
                              void* d_out, int out_size) {
    (void)in_sizes; (void)n_in; (void)out_size;
    const float* emb = (const float*)d_in[0];
    const unsigned int* labw = (const unsigned int*)d_in[1];

    float* out = (float*)d_out;
    float* pos_dist  = out;
    float* neg_dist  = out + (size_t)NDOM * NB;
    float* pos_embed = out + (size_t)2 * NDOM * NB;
    float* neg_embed = pos_embed + (size_t)NDOM * NB * NF;

    convert_labels_kernel<<<1, 256>>>(labw, NDOM * NB);
    split_kernel<<<(NDOM * NB * NF / 4) / 256, 256>>>(emb);

    cudaFuncSetAttribute(mine_kernel,
                         cudaFuncAttributeMaxDynamicSharedMemorySize, SMEM_BYTES);
    dim3 grid(NB / BM, NDOM);
    mine_kernel<<<grid, NTHREADS, SMEM_BYTES>>>(emb, pos_dist, neg_dist,
                                                pos_embed, neg_embed);

    cudaFuncSetAttribute(refine2_kernel,
                         cudaFuncAttributeMaxDynamicSharedMemorySize, SMEM2_BYTES);
    dim3 rgrid(MAXF / 128, NSLICE, NDOM);
    refine2_kernel<<<rgrid, NTHREADS, SMEM2_BYTES>>>();

    dim3 mgrid(MAXF / 8, NDOM);
    refine2_merge<<<mgrid, 256>>>(emb, pos_dist, neg_dist, pos_embed, neg_embed);

    refine3_scan<<<128, 256>>>(emb);
    refine3_write<<<64, NF>>>(emb, pos_dist, neg_dist, pos_embed, neg_embed);
}

// round 12
// speedup vs baseline: 2.1977x; 1.1064x over previous
#include <cuda_runtime.h>
#include <cuda_fp16.h>
#include <cstdint>

#define NDOM 4
#define NB   8192
#define NF   128
#define BM   128
#define BN   128
#define NT   (NB / BN)
#define NTHREADS 512
#define MARGIN1 0.022f
#define MARGIN2 2e-4f
#define MAXF  4096
#define MAXF3 2048
#define NSLICE 8
#define DOMBYTES 2097152u
#define TILEBYTES 32768u
#define JT 16                  /* tiles per job (quarter) */

// ---------------- SMEM layouts ----------------
// mine kernel: A 32K | B 2x32K | mbarriers
#define OFF_A   0u
#define OFF_B   32768u
#define OFF_MB  98304u         /* barA, full0, full1, empty0, empty1 */
#define SMEM_BYTES 98344u
// refine2 kernel (unchanged from round 11)
#define R_AH   0u
#define R_AL   32768u
#define R_B    65536u
#define R_SCR  196608u
#define R_ROWS 212992u
#define R_LABS 213504u
#define R_MB   214016u
#define SMEM2_BYTES 214032u

__device__ int g_labels[NDOM * NB];
__device__ int g_fcnt[NDOM];
__device__ int g_flags1[NDOM * MAXF];
__device__ int g_fcnt3;
__device__ int g_flags3[MAXF3];
__device__ unsigned long long g_best[MAXF3];
// tile-swizzled fp16: d*DOMBYTES + T*32768 + rr*256 + ((kc*16)^((rr&7)<<4))
__device__ __half g_hi[NDOM * NB * NF];
__device__ __half g_lo[NDOM * NB * NF];
__device__ float g_rp[(size_t)NDOM * MAXF * NSLICE * 8];
// per-row partials: [d*NB+row][slot 0..15][8 floats: p1,p2,i1,n1,n2,j1,-,-]
__device__ float g_part[(size_t)NDOM * NB * 16 * 8];   // 16MB

// ---------------- helpers ----------------
__device__ __forceinline__ uint32_t smem_u32(const void* p) {
    uint32_t a;
    asm("{ .reg .u64 t; cvta.to.shared.u64 t, %1; cvt.u32.u64 %0, t; }"
        : "=r"(a) : "l"(p));
    return a;
}
__device__ __forceinline__ uint32_t fkey(float v) {
    uint32_t u = __float_as_uint(v);
    return (u & 0x80000000u) ? ~u : (u | 0x80000000u);
}
__device__ __forceinline__ void ldsm4(uint32_t* r, uint32_t addr) {
    asm volatile("ldmatrix.sync.aligned.m8n8.x4.shared.b16 {%0,%1,%2,%3}, [%4];"
                 : "=r"(r[0]), "=r"(r[1]), "=r"(r[2]), "=r"(r[3]) : "r"(addr));
}
__device__ __forceinline__ void mma16816(float* d, const uint32_t* a,
                                         const uint32_t* b) {
    asm volatile(
        "mma.sync.aligned.m16n8k16.row.col.f32.f16.f16.f32 "
        "{%0,%1,%2,%3}, {%4,%5,%6,%7}, {%8,%9}, {%0,%1,%2,%3};"
        : "+f"(d[0]), "+f"(d[1]), "+f"(d[2]), "+f"(d[3])
        : "r"(a[0]), "r"(a[1]), "r"(a[2]), "r"(a[3]), "r"(b[0]), "r"(b[1]));
}

#define MBAR_INIT(mb, c) \
    asm volatile("mbarrier.init.shared.b64 [%0], %1;" :: "r"(mb), "r"(c) : "memory")
#define MBAR_EXPECT(mb, tx) \
    asm volatile("mbarrier.arrive.expect_tx.shared.b64 _, [%0], %1;" :: "r"(mb), "r"(tx) : "memory")
#define MBAR_ARRIVE(mb) \
    asm volatile("mbarrier.arrive.shared.b64 _, [%0];" :: "r"(mb) : "memory")
#define BULK_G2S(dst, src, size, mb) \
    asm volatile("cp.async.bulk.shared::cluster.global.mbarrier::complete_tx::bytes [%0], [%1], %2, [%3];" \
                 :: "r"(dst), "l"(src), "r"(size), "r"(mb) : "memory")
#define FENCE_ASYNC() asm volatile("fence.proxy.async.shared::cta;" ::: "memory")
#define MBAR_WAIT(mb, ph) do {                                                          \
    uint32_t _done;                                                                     \
    asm volatile("{ .reg .pred p; mbarrier.try_wait.parity.acquire.cta.shared::cta.b64 p, [%1], %2; selp.b32 %0, 1, 0, p; }" \
                 : "=r"(_done) : "r"(mb), "r"((uint32_t)(ph)) : "memory");              \
    while (!_done) {                                                                    \
        asm volatile("{ .reg .pred p; mbarrier.try_wait.parity.acquire.cta.shared::cta.b64 p, [%1], %2, 0x989680; selp.b32 %0, 1, 0, p; }" \
                     : "=r"(_done) : "r"(mb), "r"((uint32_t)(ph)) : "memory");          \
    }                                                                                   \
} while (0)

#define MERGE_MIN(P1, P2, I1, q1, q2, qi) \
    do { if ((q1) < (P1)) { P2 = fminf(P1, q2); P1 = q1; I1 = qi; } \
         else { P2 = fminf(P2, q1); } } while (0)
#define MERGE_MAX(N1, N2, J1, m1, m2, mi) \
    do { if ((m1) > (N1)) { N2 = fmaxf(N1, m2); N1 = m1; J1 = mi; } \
         else { N2 = fmaxf(N2, m1); } } while (0)

// ---------------- one-shot fp32 -> tile-swizzled fp16 hi/lo ----------------
__global__ void split_kernel(const float* __restrict__ emb) {
    const int i = blockIdx.x * blockDim.x + threadIdx.x;
    const float4 v = reinterpret_cast<const float4*>(emb)[i];
    const __half hx = __float2half_rn(v.x), hy = __float2half_rn(v.y);
    const __half hz = __float2half_rn(v.z), hw = __float2half_rn(v.w);
    const __half lx = __float2half_rn(v.x - __half2float(hx));
    const __half ly = __float2half_rn(v.y - __half2float(hy));
    const __half lz = __float2half_rn(v.z - __half2float(hz));
    const __half lw = __float2half_rn(v.w - __half2float(hw));
    uint2 hv, lv;
    hv.x = ((uint32_t)__half_as_ushort(hx)) | ((uint32_t)__half_as_ushort(hy) << 16);
    hv.y = ((uint32_t)__half_as_ushort(hz)) | ((uint32_t)__half_as_ushort(hw) << 16);
    lv.x = ((uint32_t)__half_as_ushort(lx)) | ((uint32_t)__half_as_ushort(ly) << 16);
    lv.y = ((uint32_t)__half_as_ushort(lz)) | ((uint32_t)__half_as_ushort(lw) << 16);

    const int r = i >> 5;
    const int k0 = (i & 31) * 4;
    const int rr = r & 127;
    const size_t gbyte = (size_t)(r >> 7) * TILEBYTES + (size_t)rr * 256u
        + ((((uint32_t)(k0 >> 3) << 4) ^ (((uint32_t)rr & 7u) << 4))
           + (((uint32_t)k0 & 7u) << 1));
    *reinterpret_cast<uint2*>(reinterpret_cast<char*>(g_hi) + gbyte) = hv;
    *reinterpret_cast<uint2*>(reinterpret_cast<char*>(g_lo) + gbyte) = lv;
}

// ---------------- label normalization + counters reset ----------------
__global__ void convert_labels_kernel(const unsigned int* __restrict__ w, int n) {
    __shared__ int s_any;
    if (threadIdx.x == 0) { s_any = 0; g_fcnt3 = 0; }
    if (threadIdx.x < NDOM) g_fcnt[threadIdx.x] = 0;
    __syncthreads();
    int any = 0;
    for (int i = threadIdx.x; i < n / 2; i += blockDim.x)
        any |= (w[2 * i + 1] != 0u);
    if (any) atomicOr(&s_any, 1);
    for (int i = threadIdx.x; i < MAXF3; i += blockDim.x) g_best[i] = 0ull;
    __syncthreads();
    const bool is64 = (s_any == 0);
    for (int i = threadIdx.x; i < n; i += blockDim.x)
        g_labels[i] = is64 ? (int)w[2 * i] : (int)w[i];
}

// ---------------- L1: quarter-job HMMA GEMM + top-2 mining -> partials ----------------
__global__ __launch_bounds__(NTHREADS, 1)
void mine_kernel() {
    extern __shared__ char smem[];
    const uint32_t sb = smem_u32(smem);
    const int tid = threadIdx.x;
    const int w = tid >> 5, L = tid & 31;
    const int wm = w & 3, wn = w >> 2;
    const int job = blockIdx.x;
    const int d = job >> 8;
    const int rem = job & 255;
    const int tbi = rem >> 2, q = rem & 3;
    const int tb = tbi * BM;
    const int t0 = q * JT;

    const char* __restrict__ gtiles =
        reinterpret_cast<const char*>(g_hi) + (size_t)d * DOMBYTES;
    const int* __restrict__ labd = g_labels + d * NB;

    const uint32_t barA   = sb + OFF_MB;
    const uint32_t fullB  = sb + OFF_MB + 8;    // full0, full1
    const uint32_t emptyB = sb + OFF_MB + 24;   // empty0, empty1
    if (tid == 0) {
        MBAR_INIT(barA, 1);
        MBAR_INIT(fullB, 1);  MBAR_INIT(fullB + 8, 1);
        MBAR_INIT(emptyB, 16); MBAR_INIT(emptyB + 8, 16);
    }
    FENCE_ASYNC();
    __syncthreads();
    if (tid == 0) {
        MBAR_EXPECT(barA, TILEBYTES);
        BULK_G2S(sb + OFF_A, gtiles + (size_t)tbi * TILEBYTES, TILEBYTES, barA);
        MBAR_EXPECT(fullB, TILEBYTES);
        BULK_G2S(sb + OFF_B, gtiles + (size_t)t0 * TILEBYTES, TILEBYTES, fullB);
    }

    const uint32_t cxA = ((uint32_t)(L >> 4) * 16u) ^ (((uint32_t)L & 7u) << 4);
    const uint32_t cxB = ((uint32_t)((L >> 3) & 1) * 16u) ^ (((uint32_t)L & 7u) << 4);
    uint32_t aBase[2];
#pragma unroll
    for (int mt = 0; mt < 2; ++mt) {
        const int rowA = wm * 32 + mt * 16 + (L & 7) + ((L >> 3) & 1) * 8;
        aBase[mt] = sb + OFF_A + (uint32_t)rowA * 256u;
    }
    uint32_t bRow[2];
#pragma unroll
    for (int bi = 0; bi < 2; ++bi) {
        const int rowB = wn * 32 + bi * 16 + (L & 7) + (L >> 4) * 8;
        bRow[bi] = (uint32_t)rowB * 256u;
    }

    const int rbase = wm * 32 + (L >> 2);
    int li[4];
#pragma unroll
    for (int s = 0; s < 4; ++s)
        li[s] = labd[tb + rbase + (s & 1) * 8 + (s >> 1) * 16];

    const float INF = __int_as_float(0x7f800000);
    float p1[4], p2[4], n1[4], n2[4];
    int i1[4], j1[4];
#pragma unroll
    for (int s = 0; s < 4; ++s) {
        p1[s] = INF; p2[s] = INF; n1[s] = -INF; n2[s] = -INF;
        i1[s] = -1; j1[s] = -1;
    }

    MBAR_WAIT(barA, 0);

    for (int tt = 0; tt < JT; ++tt) {
        const int t = t0 + tt;
        // issue tile t+1 into the other buffer; producer waits consumers done
        if (tt + 1 < JT && tid == 0) {
            const uint32_t b2 = (uint32_t)((tt + 1) & 1) * 8u;
            if (tt >= 1) MBAR_WAIT(emptyB + b2, ((tt - 1) >> 1) & 1);
            MBAR_EXPECT(fullB + b2, TILEBYTES);
            BULK_G2S(sb + OFF_B + (uint32_t)((tt + 1) & 1) * TILEBYTES,
                     gtiles + (size_t)(t + 1) * TILEBYTES, TILEBYTES, fullB + b2);
        }

        // column labels (global/L2, independent of B smem)
        const int jb = t * BN + wn * 32 + (L & 3) * 2;
        int labc[4][2];
#pragma unroll
        for (int nt = 0; nt < 4; ++nt) {
            const int2 lv = *reinterpret_cast<const int2*>(labd + jb + nt * 8);
            labc[nt][0] = lv.x; labc[nt][1] = lv.y;
        }

        MBAR_WAIT(fullB + (uint32_t)(tt & 1) * 8u, (tt >> 1) & 1);

        float acc[2][4][4];
#pragma unroll
        for (int mt = 0; mt < 2; ++mt)
#pragma unroll
            for (int nt = 0; nt < 4; ++nt)
#pragma unroll
                for (int r = 0; r < 4; ++r) acc[mt][nt][r] = 0.0f;

        const uint32_t sbB = sb + OFF_B + (uint32_t)(tt & 1) * TILEBYTES;
#pragma unroll
        for (int ks = 0; ks < 8; ++ks) {
            const uint32_t offA = ((uint32_t)ks * 32u) ^ cxA;
            const uint32_t offB = ((uint32_t)ks * 32u) ^ cxB;
            uint32_t A[2][4], B[2][4];
            ldsm4(A[0], aBase[0] + offA);
            ldsm4(A[1], aBase[1] + offA);
            ldsm4(B[0], sbB + bRow[0] + offB);
            ldsm4(B[1], sbB + bRow[1] + offB);
#pragma unroll
            for (int bi = 0; bi < 2; ++bi)
#pragma unroll
                for (int mt = 0; mt < 2; ++mt) {
                    mma16816(acc[mt][2 * bi],     A[mt], B[bi]);
                    mma16816(acc[mt][2 * bi + 1], A[mt], B[bi] + 2);
                }
        }
        // this warp is done reading buf tt&1
        if (L == 0) MBAR_ARRIVE(emptyB + (uint32_t)(tt & 1) * 8u);

        // fused top-2 mining (overlaps next tile's bulk load)
#pragma unroll
        for (int nt = 0; nt < 4; ++nt)
#pragma unroll
            for (int e = 0; e < 2; ++e) {
                const int lj = labc[nt][e];
                const int j = jb + nt * 8 + e;
#pragma unroll
                for (int s = 0; s < 4; ++s) {
                    const float v = acc[s >> 1][nt][(s & 1) * 2 + e];
                    if (lj == li[s]) {
                        const int growr = tb + rbase + (s & 1) * 8 + (s >> 1) * 16;
                        if (j != growr) {
                            if (v < p1[s]) { p2[s] = p1[s]; p1[s] = v; i1[s] = j; }
                            else if (v < p2[s]) p2[s] = v;
                        }
                    } else {
                        if (v > n1[s]) { n2[s] = n1[s]; n1[s] = v; j1[s] = j; }
                        else if (v > n2[s]) n2[s] = v;
                    }
                }
            }
    }

    // reduce across the 4 lanes sharing each row (xor 1,2)
#pragma unroll
    for (int s = 0; s < 4; ++s) {
#pragma unroll
        for (int off = 1; off <= 2; off <<= 1) {
            const float q1 = __shfl_xor_sync(~0u, p1[s], off);
            const float q2 = __shfl_xor_sync(~0u, p2[s], off);
            const int   qi = __shfl_xor_sync(~0u, i1[s], off);
            const float m1 = __shfl_xor_sync(~0u, n1[s], off);
            const float m2 = __shfl_xor_sync(~0u, n2[s], off);
            const int   mi = __shfl_xor_sync(~0u, j1[s], off);
            MERGE_MIN(p1[s], p2[s], i1[s], q1, q2, qi);
            MERGE_MAX(n1[s], n2[s], j1[s], m1, m2, mi);
        }
    }

    // barrier-free partial write: slot = q*4 + wn (each written exactly once)
    if ((L & 3) == 0) {
#pragma unroll
        for (int s = 0; s < 4; ++s) {
            const int row = tb + rbase + (s & 1) * 8 + (s >> 1) * 16;
            float4* dst = reinterpret_cast<float4*>(
                g_part + (((size_t)(d * NB + row)) * 16 + q * 4 + wn) * 8);
            dst[0] = make_float4(p1[s], p2[s], __int_as_float(i1[s]), n1[s]);
            dst[1] = make_float4(n2[s], __int_as_float(j1[s]), 0.f, 0.f);
        }
    }
}

// ---------------- merge 16 partials per row, write outputs, flag margins ----------------
__global__ void merge_kernel(const float* __restrict__ emb,
                             float* __restrict__ pos_dist,
                             float* __restrict__ neg_dist,
                             float* __restrict__ pos_embed,
                             float* __restrict__ neg_embed) {
    const int gw = (blockIdx.x * blockDim.x + threadIdx.x) >> 5;
    const int L = threadIdx.x & 31;
    const float INF = __int_as_float(0x7f800000);

    float P1 = INF, P2 = INF, N1 = -INF, N2 = -INF;
    int I1 = -1, J1 = -1;
    if (L < 16) {
        const float4* bp = reinterpret_cast<const float4*>(
            g_part + ((size_t)gw * 16 + L) * 8);
        const float4 a = bp[0], b = bp[1];
        P1 = a.x; P2 = a.y; I1 = __float_as_int(a.z);
        N1 = a.w; N2 = b.x; J1 = __float_as_int(b.y);
    }
#pragma unroll
    for (int off = 1; off <= 8; off <<= 1) {
        const float q1 = __shfl_xor_sync(~0u, P1, off);
        const float q2 = __shfl_xor_sync(~0u, P2, off);
        const int   qi = __shfl_xor_sync(~0u, I1, off);
        const float m1 = __shfl_xor_sync(~0u, N1, off);
        const float m2 = __shfl_xor_sync(~0u, N2, off);
        const int   mi = __shfl_xor_sync(~0u, J1, off);
        MERGE_MIN(P1, P2, I1, q1, q2, qi);
        MERGE_MAX(N1, N2, J1, m1, m2, mi);
    }

    const int d = gw >> 13, row = gw & (NB - 1);
    const int I1b = __shfl_sync(~0u, I1, 0);
    const int J1b = __shfl_sync(~0u, J1, 0);
    const bool has_pos = (I1b >= 0);
    if (L == 0) {
        pos_dist[gw] = has_pos ? P1 : 0.0f;
        neg_dist[gw] = has_pos ? N1 : 0.0f;
        if (has_pos) {
            const int code = row << 1;
            if (P2 - P1 < MARGIN1) {
                const int x = atomicAdd(&g_fcnt[d], 1);
                if (x < MAXF) g_flags1[d * MAXF + x] = code | 0;
            }
            if (N1 - N2 < MARGIN1) {
                const int x = atomicAdd(&g_fcnt[d], 1);
                if (x < MAXF) g_flags1[d * MAXF + x] = code | 1;
            }
        }
    }
    float4* pdst = reinterpret_cast<float4*>(pos_embed + (size_t)gw * NF);
    float4* ndst = reinterpret_cast<float4*>(neg_embed + (size_t)gw * NF);
    if (has_pos) {
        pdst[L] = reinterpret_cast<const float4*>(emb + ((size_t)d * NB + I1b) * NF)[L];
        ndst[L] = reinterpret_cast<const float4*>(emb + ((size_t)d * NB + J1b) * NF)[L];
    } else {
        const float4 z = make_float4(0.f, 0.f, 0.f, 0.f);
        pdst[L] = z; ndst[L] = z;
    }
}

// ---------------- L2: batched 3-pass MMA refine (unchanged from R11) ----------------
__global__ __launch_bounds__(NTHREADS, 1)
void refine2_kernel() {
    extern __shared__ char smem[];
    const uint32_t sb = smem_u32(smem);
    const int tid = threadIdx.x;
    const int w = tid >> 5, L = tid & 31;
    const int wm = w & 3, wn = w >> 2;
    const int d = blockIdx.z, grp = blockIdx.x, slice = blockIdx.y;

    const int cnt = min(g_fcnt[d], MAXF);
    const int base = grp * 128;
    int nf = cnt - base;
    if (nf <= 0) return;
    if (nf > 128) nf = 128;

    const char* __restrict__ ghT =
        reinterpret_cast<const char*>(g_hi) + (size_t)d * DOMBYTES;
    const char* __restrict__ glT =
        reinterpret_cast<const char*>(g_lo) + (size_t)d * DOMBYTES;
    const int* __restrict__ labd = g_labels + d * NB;

    const uint32_t bar0 = sb + R_MB;
    if (tid == 0) { MBAR_INIT(bar0, 1); MBAR_INIT(bar0 + 8, 1); }
    FENCE_ASYNC();
    __syncthreads();

    const int t0 = slice * (NT / NSLICE);
    if (tid == 0) {
        MBAR_EXPECT(bar0, 2 * TILEBYTES);
        BULK_G2S(sb + R_B, ghT + (size_t)t0 * TILEBYTES, TILEBYTES, bar0);
        BULK_G2S(sb + R_B + TILEBYTES, glT + (size_t)t0 * TILEBYTES, TILEBYTES, bar0);
    }

    int* rows_s = reinterpret_cast<int*>(smem + R_ROWS);
    int* labs_s = reinterpret_cast<int*>(smem + R_LABS);
    if (tid < 128) {
        const int code = g_flags1[d * MAXF + base + ((tid < nf) ? tid : 0)];
        rows_s[tid] = code >> 1;
    }
    __syncthreads();
    if (tid < 128) labs_s[tid] = labd[rows_s[tid]];

#pragma unroll
    for (int it = 0; it < 8; ++it) {
        const int c = it * NTHREADS + tid;
        const int comp = c >> 11;
        const int rem = c & 2047;
        const int f = rem >> 4, kc = rem & 15;
        const int row = rows_s[f];
        const size_t srcb = (size_t)(row >> 7) * TILEBYTES + (size_t)(row & 127) * 256u
            + (((uint32_t)kc * 16u) ^ (((uint32_t)row & 7u) << 4));
        const uint4 v = *reinterpret_cast<const uint4*>((comp ? glT : ghT) + srcb);
        const uint32_t dstb = (uint32_t)f * 256u
            + (((uint32_t)kc * 16u) ^ (((uint32_t)f & 7u) << 4));
        *reinterpret_cast<uint4*>(smem + (comp ? R_AL : R_AH) + dstb) = v;
    }

    const uint32_t cxA = ((uint32_t)(L >> 4) * 16u) ^ (((uint32_t)L & 7u) << 4);
    const uint32_t cxB = ((uint32_t)((L >> 3) & 1) * 16u) ^ (((uint32_t)L & 7u) << 4);
    uint32_t aBase[2];
#pragma unroll
    for (int mt = 0; mt < 2; ++mt) {
        const int rowA = wm * 32 + mt * 16 + (L & 7) + ((L >> 3) & 1) * 8;
        aBase[mt] = sb + R_AH + (uint32_t)rowA * 256u;
    }
    uint32_t bRow[2];
#pragma unroll
    for (int bi = 0; bi < 2; ++bi) {
        const int rowB = wn * 32 + bi * 16 + (L & 7) + (L >> 4) * 8;
        bRow[bi] = (uint32_t)rowB * 256u;
    }

    const int rbase = wm * 32 + (L >> 2);
    int li[4], rid[4];
#pragma unroll
    for (int s = 0; s < 4; ++s) {
        const int f = rbase + (s & 1) * 8 + (s >> 1) * 16;
        li[s] = labs_s[f];
        rid[s] = rows_s[f];
    }
    __syncthreads();

    const float INF = __int_as_float(0x7f800000);
    float p1[4], p2[4], n1[4], n2[4];
    int i1[4], j1[4];
#pragma unroll
    for (int s = 0; s < 4; ++s) {
        p1[s] = INF; p2[s] = INF; n1[s] = -INF; n2[s] = -INF;
        i1[s] = -1; j1[s] = -1;
    }

    for (int tt = 0; tt < NT / NSLICE; ++tt) {
        const int t = t0 + tt;
        if (tt + 1 < NT / NSLICE && tid == 0) {
            const uint32_t bn_ = bar0 + (uint32_t)((tt + 1) & 1) * 8u;
            const uint32_t bo = sb + R_B + (uint32_t)((tt + 1) & 1) * 65536u;
            MBAR_EXPECT(bn_, 2 * TILEBYTES);
            BULK_G2S(bo, ghT + (size_t)(t + 1) * TILEBYTES, TILEBYTES, bn_);
            BULK_G2S(bo + TILEBYTES, glT + (size_t)(t + 1) * TILEBYTES, TILEBYTES, bn_);
        }
        MBAR_WAIT(bar0 + (uint32_t)(tt & 1) * 8u, (tt >> 1) & 1);

        const int jb = t * BN + wn * 32 + (L & 3) * 2;
        int labc[4][2];
#pragma unroll
        for (int nt = 0; nt < 4; ++nt) {
            const int2 lv = *reinterpret_cast<const int2*>(labd + jb + nt * 8);
            labc[nt][0] = lv.x; labc[nt][1] = lv.y;
        }

        float acc[2][4][4];
#pragma unroll
        for (int mt = 0; mt < 2; ++mt)
#pragma unroll
            for (int nt = 0; nt < 4; ++nt)
#pragma unroll
                for (int r = 0; r < 4; ++r) acc[mt][nt][r] = 0.0f;

        const uint32_t sbB = sb + R_B + (uint32_t)(tt & 1) * 65536u;
#pragma unroll
        for (int ks = 0; ks < 8; ++ks) {
            const uint32_t offA = ((uint32_t)ks * 32u) ^ cxA;
            const uint32_t offB = ((uint32_t)ks * 32u) ^ cxB;
            uint32_t Ah[2][4], Al[2][4], Bh[2][4], Bl[2][4];
            ldsm4(Ah[0], aBase[0] + offA);
            ldsm4(Ah[1], aBase[1] + offA);
            ldsm4(Bh[0], sbB + bRow[0] + offB);
            ldsm4(Bh[1], sbB + bRow[1] + offB);
            ldsm4(Al[0], aBase[0] + 32768u + offA);
            ldsm4(Al[1], aBase[1] + 32768u + offA);
            ldsm4(Bl[0], sbB + TILEBYTES + bRow[0] + offB);
            ldsm4(Bl[1], sbB + TILEBYTES + bRow[1] + offB);
#pragma unroll
            for (int bi = 0; bi < 2; ++bi)
#pragma unroll
                for (int mt = 0; mt < 2; ++mt) {
                    mma16816(acc[mt][2 * bi],     Ah[mt], Bh[bi]);
                    mma16816(acc[mt][2 * bi + 1], Ah[mt], Bh[bi] + 2);
                }
#pragma unroll
            for (int bi = 0; bi < 2; ++bi)
#pragma unroll
                for (int mt = 0; mt < 2; ++mt) {
                    mma16816(acc[mt][2 * bi],     Al[mt], Bh[bi]);
                    mma16816(acc[mt][2 * bi + 1], Al[mt], Bh[bi] + 2);
                }
#pragma unroll
            for (int bi = 0; bi < 2; ++bi)
#pragma unroll
                for (int mt = 0; mt < 2; ++mt) {
                    mma16816(acc[mt][2 * bi],     Ah[mt], Bl[bi]);
                    mma16816(acc[mt][2 * bi + 1], Ah[mt], Bl[bi] + 2);
                }
        }

#pragma unroll
        for (int nt = 0; nt < 4; ++nt)
#pragma unroll
            for (int e = 0; e < 2; ++e) {
                const int lj = labc[nt][e];
                const int j = jb + nt * 8 + e;
#pragma unroll
                for (int s = 0; s < 4; ++s) {
                    const float v = acc[s >> 1][nt][(s & 1) * 2 + e];
                    if (lj == li[s]) {
                        if (j != rid[s]) {
                            if (v < p1[s]) { p2[s] = p1[s]; p1[s] = v; i1[s] = j; }
                            else if (v < p2[s]) p2[s] = v;
                        }
                    } else {
                        if (v > n1[s]) { n2[s] = n1[s]; n1[s] = v; j1[s] = j; }
                        else if (v > n2[s]) n2[s] = v;
                    }
                }
            }
        __syncthreads();
    }

#pragma unroll
    for (int s = 0; s < 4; ++s) {
#pragma unroll
        for (int off = 1; off <= 2; off <<= 1) {
            const float q1 = __shfl_xor_sync(~0u, p1[s], off);
            const float q2 = __shfl_xor_sync(~0u, p2[s], off);
            const int   qi = __shfl_xor_sync(~0u, i1[s], off);
            const float m1 = __shfl_xor_sync(~0u, n1[s], off);
            const float m2 = __shfl_xor_sync(~0u, n2[s], off);
            const int   mi = __shfl_xor_sync(~0u, j1[s], off);
            MERGE_MIN(p1[s], p2[s], i1[s], q1, q2, qi);
            MERGE_MAX(n1[s], n2[s], j1[s], m1, m2, mi);
        }
    }

    float* scr = reinterpret_cast<float*>(smem + R_SCR);
    if (wn > 0 && (L & 3) == 0) {
#pragma unroll
        for (int s = 0; s < 4; ++s) {
            const int f = rbase + (s & 1) * 8 + (s >> 1) * 16;
            float* sr = scr + (f * 4 + wn) * 8;
            sr[0] = p1[s]; sr[1] = p2[s];
            reinterpret_cast<int*>(sr)[2] = i1[s];
            sr[3] = n1[s]; sr[4] = n2[s];
            reinterpret_cast<int*>(sr)[5] = j1[s];
        }
    }
    __syncthreads();
    if (wn == 0 && (L & 3) == 0) {
#pragma unroll
        for (int s = 0; s < 4; ++s) {
            const int f = rbase + (s & 1) * 8 + (s >> 1) * 16;
            float P1 = p1[s], P2 = p2[s], N1 = n1[s], N2 = n2[s];
            int I1 = i1[s], J1 = j1[s];
#pragma unroll
            for (int o = 1; o < 4; ++o) {
                const float* sr = scr + (f * 4 + o) * 8;
                MERGE_MIN(P1, P2, I1, sr[0], sr[1], reinterpret_cast<const int*>(sr)[2]);
                MERGE_MAX(N1, N2, J1, sr[3], sr[4], reinterpret_cast<const int*>(sr)[5]);
            }
            if (f < nf) {
                float4* dst = reinterpret_cast<float4*>(
                    g_rp + (((size_t)d * MAXF + base + f) * NSLICE + slice) * 8);
                dst[0] = make_float4(P1, P2, __int_as_float(I1), N1);
                dst[1] = make_float4(N2, __int_as_float(J1), 0.f, 0.f);
            }
        }
    }
}

// ---------------- L2 merge: fold slices, write outputs, cascade to L3 ----------------
__global__ void refine2_merge(const float* __restrict__ emb,
                              float* __restrict__ pos_dist,
                              float* __restrict__ neg_dist,
                              float* __restrict__ pos_embed,
                              float* __restrict__ neg_embed) {
    const int wid = threadIdx.x >> 5, L = threadIdx.x & 31;
    const int d = blockIdx.y;
    const int x = blockIdx.x * 8 + wid;
    const int cnt = min(g_fcnt[d], MAXF);
    if (x >= cnt) return;
    const int code = g_flags1[d * MAXF + x];
    const int row = code >> 1, side = code & 1;

    const float4* bp = reinterpret_cast<const float4*>(
        g_rp + (((size_t)d * MAXF + x) * NSLICE + (L & 7)) * 8);
    const float4 a = bp[0], b = bp[1];
    float P1 = a.x, P2 = a.y, N1 = a.w, N2 = b.x;
    int I1 = __float_as_int(a.z), J1 = __float_as_int(b.y);
#pragma unroll
    for (int off = 1; off <= 4; off <<= 1) {
        const float q1 = __shfl_xor_sync(~0u, P1, off);
        const float q2 = __shfl_xor_sync(~0u, P2, off);
        const int   qi = __shfl_xor_sync(~0u, I1, off);
        const float m1 = __shfl_xor_sync(~0u, N1, off);
        const float m2 = __shfl_xor_sync(~0u, N2, off);
        const int   mi = __shfl_xor_sync(~0u, J1, off);
        MERGE_MIN(P1, P2, I1, q1, q2, qi);
        MERGE_MAX(N1, N2, J1, m1, m2, mi);
    }
    float v1 = side ? N1 : P1;
    float gap = side ? (N1 - N2) : (P2 - P1);
    int idx = side ? J1 : I1;
    v1  = __shfl_sync(~0u, v1, 0);
    gap = __shfl_sync(~0u, gap, 0);
    idx = __shfl_sync(~0u, idx, 0);
    if (idx < 0) return;

    const size_t go = (size_t)d * NB + row;
    if (L == 0) {
        (side ? neg_dist : pos_dist)[go] = v1;
        if (gap < MARGIN2) {
            const int y = atomicAdd(&g_fcnt3, 1);
            if (y < MAXF3) g_flags3[y] = (int)((go << 1) | (size_t)side);
        }
    }
    float4* dst = reinterpret_cast<float4*>(
        (side ? neg_embed : pos_embed) + go * NF);
    dst[L] = reinterpret_cast<const float4*>(
        emb + ((size_t)d * NB + idx) * NF)[L];
}

// ---------------- L3: exact fp32 full-row rescan (rare) ----------------
__global__ void refine3_scan(const float* __restrict__ emb) {
    __shared__ float srow[NF];
    __shared__ int sli;
    __shared__ unsigned long long swb[8];
    const int cnt = min(g_fcnt3, MAXF3);
    for (int f = blockIdx.x; f < cnt; f += gridDim.x) {
        const int code = g_flags3[f];
        const int side = code & 1, gr = code >> 1;
        const int d = gr >> 13, row = gr & (NB - 1);
        const float* __restrict__ embd = emb + (size_t)d * NB * NF;
        __syncthreads();
        if (threadIdx.x < NF) srow[threadIdx.x] = embd[(size_t)row * NF + threadIdx.x];
        if (threadIdx.x == 0) sli = g_labels[d * NB + row];
        __syncthreads();
        const int li = sli;
        const float4* a4 = reinterpret_cast<const float4*>(srow);

        unsigned long long best = 0ull;
        for (int j = threadIdx.x; j < NB; j += blockDim.x) {
            const int lj = g_labels[d * NB + j];
            const bool valid = side ? (lj != li) : (lj == li && j != row);
            if (!valid) continue;
            const float4* b4 = reinterpret_cast<const float4*>(embd + (size_t)j * NF);
            float accv = 0.0f;
#pragma unroll
            for (int qq = 0; qq < 32; ++qq) {
                const float4 av = a4[qq], bv = b4[qq];
                accv = fmaf(av.x, bv.x, accv);
                accv = fmaf(av.y, bv.y, accv);
                accv = fmaf(av.z, bv.z, accv);
                accv = fmaf(av.w, bv.w, accv);
            }
            uint32_t key = fkey(accv);
            if (!side) key = ~key;
            const unsigned long long pk =
                ((unsigned long long)key << 32) | (uint32_t)(NB - 1 - j);
            if (pk > best) best = pk;
        }
#pragma unroll
        for (int off = 16; off > 0; off >>= 1) {
            const unsigned long long o = __shfl_xor_sync(~0u, best, off);
            if (o > best) best = o;
        }
        if ((threadIdx.x & 31) == 0) swb[threadIdx.x >> 5] = best;
        __syncthreads();
        if (threadIdx.x == 0) {
            unsigned long long b = swb[0];
#pragma unroll
            for (int o = 1; o < 8; ++o) if (swb[o] > b) b = swb[o];
            g_best[f] = b;
        }
    }
}

__global__ void refine3_write(const float* __restrict__ emb,
                              float* __restrict__ pos_dist,
                              float* __restrict__ neg_dist,
                              float* __restrict__ pos_embed,
                              float* __restrict__ neg_embed) {
    const int cnt = min(g_fcnt3, MAXF3);
    for (int f = blockIdx.x; f < cnt; f += gridDim.x) {
        const int code = g_flags3[f];
        const int side = code & 1, gr = code >> 1;
        const int d = gr >> 13, row = gr & (NB - 1);
        const unsigned long long pk = g_best[f];
        if (pk == 0ull) continue;
        const uint32_t key = (uint32_t)(pk >> 32);
        const int j = NB - 1 - (int)(pk & 0xFFFFFFFFull);
        const uint32_t m = side ? key : ~key;
        const uint32_t u = (m & 0x80000000u) ? (m & 0x7FFFFFFFu) : ~m;
        const float v = __uint_as_float(u);

        const size_t go = (size_t)d * NB + row;
        float* dist = side ? neg_dist : pos_dist;
        float* embo = side ? neg_embed : pos_embed;
        if (threadIdx.x == 0) dist[go] = v;
        embo[go * NF + threadIdx.x] = emb[((size_t)d * NB + j) * NF + threadIdx.x];
    }
}

// ---------------- launch ----------------
extern "C" void kernel_launch(void* const* d_in, const int* in_sizes, int n_in,
                              void* d_out, int out_size) {
    (void)in_sizes; (void)n_in; (void)out_size;
    const float* emb = (const float*)d_in[0];
    const unsigned int* labw = (const unsigned int*)d_in[1];

    float* out = (float*)d_out;
    float* pos_dist  = out;
    float* neg_dist  = out + (size_t)NDOM * NB;
    float* pos_embed = out + (size_t)2 * NDOM * NB;
    float* neg_embed = pos_embed + (size_t)NDOM * NB * NF;

    convert_labels_kernel<<<1, 256>>>(labw, NDOM * NB);
    split_kernel<<<(NDOM * NB * NF / 4) / 256, 256>>>(emb);

    cudaFuncSetAttribute(mine_kernel,
                         cudaFuncAttributeMaxDynamicSharedMemorySize, SMEM_BYTES);
    mine_kernel<<<NDOM * 256, NTHREADS, SMEM_BYTES>>>();

    merge_kernel<<<(NDOM * NB * 32) / 256, 256>>>(emb, pos_dist, neg_dist,
                                                  pos_embed, neg_embed);

    cudaFuncSetAttribute(refine2_kernel,
                         cudaFuncAttributeMaxDynamicSharedMemorySize, SMEM2_BYTES);
    dim3 rgrid(MAXF / 128, NSLICE, NDOM);
    refine2_kernel<<<rgrid, NTHREADS, SMEM2_BYTES>>>();

    dim3 mgrid(MAXF / 8, NDOM);
    refine2_merge<<<mgrid, 256>>>(emb, pos_dist, neg_dist, pos_embed, neg_embed);

    refine3_scan<<<128, 256>>>(emb);
    refine3_write<<<64, NF>>>(emb, pos_dist, neg_dist, pos_embed, neg_embed);
}

// round 13
// speedup vs baseline: 2.2849x; 1.0397x over previous
#include <cuda_runtime.h>
#include <cuda_fp16.h>
#include <cstdint>

#define NDOM 4
#define NB   8192
#define NF   128
#define BM   128
#define BN   128
#define NT   (NB / BN)
#define NTHREADS 512
#define MARGIN1 0.022f
#define MARGIN2 2e-4f
#define MAXF  4096
#define MAXF3 2048
#define NSLICE 16
#define DOMBYTES 2097152u
#define TILEBYTES 32768u
#define JT 16

// ---------------- SMEM layouts ----------------
// mine kernel: A 32K | B 4x32K | mbarriers (barA, full[4], empty[4])
#define OFF_A   0u
#define OFF_B   32768u
#define OFF_MB  163840u
#define SMEM_BYTES 163928u
// refine2 kernel
#define R_AH   0u
#define R_AL   32768u
#define R_B    65536u
#define R_SCR  196608u
#define R_ROWS 212992u
#define R_LABS 213504u
#define R_MB   214016u
#define SMEM2_BYTES 214032u

__device__ int g_labels[NDOM * NB];
__device__ int g_fcnt[NDOM];
__device__ int g_flags1[NDOM * MAXF];
__device__ int g_fcnt3;
__device__ int g_flags3[MAXF3];
__device__ unsigned long long g_best[MAXF3];
// tile-swizzled fp16: d*DOMBYTES + T*32768 + rr*256 + ((kc*16)^((rr&7)<<4))
__device__ __half g_hi[NDOM * NB * NF];
__device__ __half g_lo[NDOM * NB * NF];
__device__ float g_rp[(size_t)NDOM * MAXF * NSLICE * 8];
// per-row partials: [d*NB+row][slot 0..15][8 floats]
__device__ float g_part[(size_t)NDOM * NB * 16 * 8];

// ---------------- helpers ----------------
__device__ __forceinline__ uint32_t smem_u32(const void* p) {
    uint32_t a;
    asm("{ .reg .u64 t; cvta.to.shared.u64 t, %1; cvt.u32.u64 %0, t; }"
        : "=r"(a) : "l"(p));
    return a;
}
__device__ __forceinline__ uint32_t fkey(float v) {
    uint32_t u = __float_as_uint(v);
    return (u & 0x80000000u) ? ~u : (u | 0x80000000u);
}
__device__ __forceinline__ void ldsm4(uint32_t* r, uint32_t addr) {
    asm volatile("ldmatrix.sync.aligned.m8n8.x4.shared.b16 {%0,%1,%2,%3}, [%4];"
                 : "=r"(r[0]), "=r"(r[1]), "=r"(r[2]), "=r"(r[3]) : "r"(addr));
}
__device__ __forceinline__ void mma16816(float* d, const uint32_t* a,
                                         const uint32_t* b) {
    asm volatile(
        "mma.sync.aligned.m16n8k16.row.col.f32.f16.f16.f32 "
        "{%0,%1,%2,%3}, {%4,%5,%6,%7}, {%8,%9}, {%0,%1,%2,%3};"
        : "+f"(d[0]), "+f"(d[1]), "+f"(d[2]), "+f"(d[3])
        : "r"(a[0]), "r"(a[1]), "r"(a[2]), "r"(a[3]), "r"(b[0]), "r"(b[1]));
}

#define MBAR_INIT(mb, c) \
    asm volatile("mbarrier.init.shared.b64 [%0], %1;" :: "r"(mb), "r"(c) : "memory")
#define MBAR_EXPECT(mb, tx) \
    asm volatile("mbarrier.arrive.expect_tx.shared.b64 _, [%0], %1;" :: "r"(mb), "r"(tx) : "memory")
#define MBAR_ARRIVE(mb) \
    asm volatile("mbarrier.arrive.shared.b64 _, [%0];" :: "r"(mb) : "memory")
#define BULK_G2S(dst, src, size, mb) \
    asm volatile("cp.async.bulk.shared::cluster.global.mbarrier::complete_tx::bytes [%0], [%1], %2, [%3];" \
                 :: "r"(dst), "l"(src), "r"(size), "r"(mb) : "memory")
#define FENCE_ASYNC() asm volatile("fence.proxy.async.shared::cta;" ::: "memory")
#define MBAR_WAIT(mb, ph) do {                                                          \
    uint32_t _done;                                                                     \
    asm volatile("{ .reg .pred p; mbarrier.try_wait.parity.acquire.cta.shared::cta.b64 p, [%1], %2; selp.b32 %0, 1, 0, p; }" \
                 : "=r"(_done) : "r"(mb), "r"((uint32_t)(ph)) : "memory");              \
    while (!_done) {                                                                    \
        asm volatile("{ .reg .pred p; mbarrier.try_wait.parity.acquire.cta.shared::cta.b64 p, [%1], %2, 0x989680; selp.b32 %0, 1, 0, p; }" \
                     : "=r"(_done) : "r"(mb), "r"((uint32_t)(ph)) : "memory");          \
    }                                                                                   \
} while (0)

#define MERGE_MIN(P1, P2, I1, q1, q2, qi) \
    do { if ((q1) < (P1)) { P2 = fminf(P1, q2); P1 = q1; I1 = qi; } \
         else { P2 = fminf(P2, q1); } } while (0)
#define MERGE_MAX(N1, N2, J1, m1, m2, mi) \
    do { if ((m1) > (N1)) { N2 = fmaxf(N1, m2); N1 = m1; J1 = mi; } \
         else { N2 = fmaxf(N2, m1); } } while (0)

// ---------------- one-shot fp32 -> tile-swizzled fp16 hi/lo ----------------
__global__ void split_kernel(const float* __restrict__ emb) {
    const int i = blockIdx.x * blockDim.x + threadIdx.x;
    const float4 v = reinterpret_cast<const float4*>(emb)[i];
    const __half hx = __float2half_rn(v.x), hy = __float2half_rn(v.y);
    const __half hz = __float2half_rn(v.z), hw = __float2half_rn(v.w);
    const __half lx = __float2half_rn(v.x - __half2float(hx));
    const __half ly = __float2half_rn(v.y - __half2float(hy));
    const __half lz = __float2half_rn(v.z - __half2float(hz));
    const __half lw = __float2half_rn(v.w - __half2float(hw));
    uint2 hv, lv;
    hv.x = ((uint32_t)__half_as_ushort(hx)) | ((uint32_t)__half_as_ushort(hy) << 16);
    hv.y = ((uint32_t)__half_as_ushort(hz)) | ((uint32_t)__half_as_ushort(hw) << 16);
    lv.x = ((uint32_t)__half_as_ushort(lx)) | ((uint32_t)__half_as_ushort(ly) << 16);
    lv.y = ((uint32_t)__half_as_ushort(lz)) | ((uint32_t)__half_as_ushort(lw) << 16);

    const int r = i >> 5;
    const int k0 = (i & 31) * 4;
    const int rr = r & 127;
    const size_t gbyte = (size_t)(r >> 7) * TILEBYTES + (size_t)rr * 256u
        + ((((uint32_t)(k0 >> 3) << 4) ^ (((uint32_t)rr & 7u) << 4))
           + (((uint32_t)k0 & 7u) << 1));
    *reinterpret_cast<uint2*>(reinterpret_cast<char*>(g_hi) + gbyte) = hv;
    *reinterpret_cast<uint2*>(reinterpret_cast<char*>(g_lo) + gbyte) = lv;
}

// ---------------- label normalization + counters reset ----------------
__global__ void convert_labels_kernel(const unsigned int* __restrict__ w, int n) {
    __shared__ int s_any;
    if (threadIdx.x == 0) { s_any = 0; g_fcnt3 = 0; }
    if (threadIdx.x < NDOM) g_fcnt[threadIdx.x] = 0;
    __syncthreads();
    int any = 0;
    for (int i = threadIdx.x; i < n / 2; i += blockDim.x)
        any |= (w[2 * i + 1] != 0u);
    if (any) atomicOr(&s_any, 1);
    for (int i = threadIdx.x; i < MAXF3; i += blockDim.x) g_best[i] = 0ull;
    __syncthreads();
    const bool is64 = (s_any == 0);
    for (int i = threadIdx.x; i < n; i += blockDim.x)
        g_labels[i] = is64 ? (int)w[2 * i] : (int)w[i];
}

// ---------------- L1: quarter-job HMMA GEMM, 4-deep pipeline ----------------
__global__ __launch_bounds__(NTHREADS, 1)
void mine_kernel() {
    extern __shared__ char smem[];
    const uint32_t sb = smem_u32(smem);
    const int tid = threadIdx.x;
    const int w = tid >> 5, L = tid & 31;
    const int wm = w & 3, wn = w >> 2;
    const int job = blockIdx.x;
    const int d = job >> 8;
    const int rem = job & 255;
    const int tbi = rem >> 2, q = rem & 3;
    const int tb = tbi * BM;
    const int t0 = q * JT;

    const char* __restrict__ gtiles =
        reinterpret_cast<const char*>(g_hi) + (size_t)d * DOMBYTES;
    const int* __restrict__ labd = g_labels + d * NB;

    const uint32_t barA   = sb + OFF_MB;
    const uint32_t fullB  = sb + OFF_MB + 8;    // full[0..3]
    const uint32_t emptyB = sb + OFF_MB + 40;   // empty[0..3]
    if (tid == 0) {
        MBAR_INIT(barA, 1);
#pragma unroll
        for (int i = 0; i < 4; ++i) {
            MBAR_INIT(fullB + i * 8, 1);
            MBAR_INIT(emptyB + i * 8, 16);
        }
    }
    FENCE_ASYNC();
    __syncthreads();
    if (tid == 0) {
        MBAR_EXPECT(barA, TILEBYTES);
        BULK_G2S(sb + OFF_A, gtiles + (size_t)tbi * TILEBYTES, TILEBYTES, barA);
#pragma unroll
        for (int i = 0; i < 3; ++i) {
            MBAR_EXPECT(fullB + i * 8, TILEBYTES);
            BULK_G2S(sb + OFF_B + (uint32_t)i * TILEBYTES,
                     gtiles + (size_t)(t0 + i) * TILEBYTES, TILEBYTES, fullB + i * 8);
        }
    }

    const uint32_t cxA = ((uint32_t)(L >> 4) * 16u) ^ (((uint32_t)L & 7u) << 4);
    const uint32_t cxB = ((uint32_t)((L >> 3) & 1) * 16u) ^ (((uint32_t)L & 7u) << 4);
    uint32_t aBase[2];
#pragma unroll
    for (int mt = 0; mt < 2; ++mt) {
        const int rowA = wm * 32 + mt * 16 + (L & 7) + ((L >> 3) & 1) * 8;
        aBase[mt] = sb + OFF_A + (uint32_t)rowA * 256u;
    }
    uint32_t bRow[2];
#pragma unroll
    for (int bi = 0; bi < 2; ++bi) {
        const int rowB = wn * 32 + bi * 16 + (L & 7) + (L >> 4) * 8;
        bRow[bi] = (uint32_t)rowB * 256u;
    }

    const int rbase = wm * 32 + (L >> 2);
    int li[4];
#pragma unroll
    for (int s = 0; s < 4; ++s)
        li[s] = labd[tb + rbase + (s & 1) * 8 + (s >> 1) * 16];

    const float INF = __int_as_float(0x7f800000);
    float p1[4], p2[4], n1[4], n2[4];
    int i1[4], j1[4];
#pragma unroll
    for (int s = 0; s < 4; ++s) {
        p1[s] = INF; p2[s] = INF; n1[s] = -INF; n2[s] = -INF;
        i1[s] = -1; j1[s] = -1;
    }

    MBAR_WAIT(barA, 0);

    for (int tt = 0; tt < JT; ++tt) {
        const int t = t0 + tt;
        // producer: issue tile tt+3 into buf (tt+3)&3 (consumed last at round tt-1)
        if (tt + 3 < JT && tid == 0) {
            const uint32_t b3 = (uint32_t)((tt + 3) & 3) * 8u;
            if (tt >= 1) MBAR_WAIT(emptyB + b3, ((tt - 1) >> 2) & 1);
            MBAR_EXPECT(fullB + b3, TILEBYTES);
            BULK_G2S(sb + OFF_B + (uint32_t)((tt + 3) & 3) * TILEBYTES,
                     gtiles + (size_t)(t + 3) * TILEBYTES, TILEBYTES, fullB + b3);
        }

        // column labels (independent of B smem)
        const int jb = t * BN + wn * 32 + (L & 3) * 2;
        int labc[4][2];
#pragma unroll
        for (int nt = 0; nt < 4; ++nt) {
            const int2 lv = *reinterpret_cast<const int2*>(labd + jb + nt * 8);
            labc[nt][0] = lv.x; labc[nt][1] = lv.y;
        }

        MBAR_WAIT(fullB + (uint32_t)(tt & 3) * 8u, (tt >> 2) & 1);

        float acc[2][4][4];
#pragma unroll
        for (int mt = 0; mt < 2; ++mt)
#pragma unroll
            for (int nt = 0; nt < 4; ++nt)
#pragma unroll
                for (int r = 0; r < 4; ++r) acc[mt][nt][r] = 0.0f;

        const uint32_t sbB = sb + OFF_B + (uint32_t)(tt & 3) * TILEBYTES;
#pragma unroll
        for (int ks = 0; ks < 8; ++ks) {
            const uint32_t offA = ((uint32_t)ks * 32u) ^ cxA;
            const uint32_t offB = ((uint32_t)ks * 32u) ^ cxB;
            uint32_t A[2][4], B[2][4];
            ldsm4(A[0], aBase[0] + offA);
            ldsm4(A[1], aBase[1] + offA);
            ldsm4(B[0], sbB + bRow[0] + offB);
            ldsm4(B[1], sbB + bRow[1] + offB);
#pragma unroll
            for (int bi = 0; bi < 2; ++bi)
#pragma unroll
                for (int mt = 0; mt < 2; ++mt) {
                    mma16816(acc[mt][2 * bi],     A[mt], B[bi]);
                    mma16816(acc[mt][2 * bi + 1], A[mt], B[bi] + 2);
                }
        }
        if (L == 0) MBAR_ARRIVE(emptyB + (uint32_t)(tt & 3) * 8u);

        // fused top-2 mining (overlaps in-flight bulk loads)
#pragma unroll
        for (int nt = 0; nt < 4; ++nt)
#pragma unroll
            for (int e = 0; e < 2; ++e) {
                const int lj = labc[nt][e];
                const int j = jb + nt * 8 + e;
#pragma unroll
                for (int s = 0; s < 4; ++s) {
                    const float v = acc[s >> 1][nt][(s & 1) * 2 + e];
                    if (lj == li[s]) {
                        const int growr = tb + rbase + (s & 1) * 8 + (s >> 1) * 16;
                        if (j != growr) {
                            if (v < p1[s]) { p2[s] = p1[s]; p1[s] = v; i1[s] = j; }
                            else if (v < p2[s]) p2[s] = v;
                        }
                    } else {
                        if (v > n1[s]) { n2[s] = n1[s]; n1[s] = v; j1[s] = j; }
                        else if (v > n2[s]) n2[s] = v;
                    }
                }
            }
    }

    // reduce across the 4 lanes sharing each row (xor 1,2)
#pragma unroll
    for (int s = 0; s < 4; ++s) {
#pragma unroll
        for (int off = 1; off <= 2; off <<= 1) {
            const float q1 = __shfl_xor_sync(~0u, p1[s], off);
            const float q2 = __shfl_xor_sync(~0u, p2[s], off);
            const int   qi = __shfl_xor_sync(~0u, i1[s], off);
            const float m1 = __shfl_xor_sync(~0u, n1[s], off);
            const float m2 = __shfl_xor_sync(~0u, n2[s], off);
            const int   mi = __shfl_xor_sync(~0u, j1[s], off);
            MERGE_MIN(p1[s], p2[s], i1[s], q1, q2, qi);
            MERGE_MAX(n1[s], n2[s], j1[s], m1, m2, mi);
        }
    }

    // barrier-free partial write: slot = q*4 + wn
    if ((L & 3) == 0) {
#pragma unroll
        for (int s = 0; s < 4; ++s) {
            const int row = tb + rbase + (s & 1) * 8 + (s >> 1) * 16;
            float4* dst = reinterpret_cast<float4*>(
                g_part + (((size_t)(d * NB + row)) * 16 + q * 4 + wn) * 8);
            dst[0] = make_float4(p1[s], p2[s], __int_as_float(i1[s]), n1[s]);
            dst[1] = make_float4(n2[s], __int_as_float(j1[s]), 0.f, 0.f);
        }
    }
}

// ---------------- merge 16 partials per row, write outputs, flag margins ----------------
__global__ void merge_kernel(const float* __restrict__ emb,
                             float* __restrict__ pos_dist,
                             float* __restrict__ neg_dist,
                             float* __restrict__ pos_embed,
                             float* __restrict__ neg_embed) {
    const int gw = (blockIdx.x * blockDim.x + threadIdx.x) >> 5;
    const int L = threadIdx.x & 31;
    const float INF = __int_as_float(0x7f800000);

    float P1 = INF, P2 = INF, N1 = -INF, N2 = -INF;
    int I1 = -1, J1 = -1;
    if (L < 16) {
        const float4* bp = reinterpret_cast<const float4*>(
            g_part + ((size_t)gw * 16 + L) * 8);
        const float4 a = bp[0], b = bp[1];
        P1 = a.x; P2 = a.y; I1 = __float_as_int(a.z);
        N1 = a.w; N2 = b.x; J1 = __float_as_int(b.y);
    }
#pragma unroll
    for (int off = 1; off <= 8; off <<= 1) {
        const float q1 = __shfl_xor_sync(~0u, P1, off);
        const float q2 = __shfl_xor_sync(~0u, P2, off);
        const int   qi = __shfl_xor_sync(~0u, I1, off);
        const float m1 = __shfl_xor_sync(~0u, N1, off);
        const float m2 = __shfl_xor_sync(~0u, N2, off);
        const int   mi = __shfl_xor_sync(~0u, J1, off);
        MERGE_MIN(P1, P2, I1, q1, q2, qi);
        MERGE_MAX(N1, N2, J1, m1, m2, mi);
    }

    const int d = gw >> 13, row = gw & (NB - 1);
    const int I1b = __shfl_sync(~0u, I1, 0);
    const int J1b = __shfl_sync(~0u, J1, 0);
    const bool has_pos = (I1b >= 0);
    if (L == 0) {
        pos_dist[gw] = has_pos ? P1 : 0.0f;
        neg_dist[gw] = has_pos ? N1 : 0.0f;
        if (has_pos) {
            const int code = row << 1;
            if (P2 - P1 < MARGIN1) {
                const int x = atomicAdd(&g_fcnt[d], 1);
                if (x < MAXF) g_flags1[d * MAXF + x] = code | 0;
            }
            if (N1 - N2 < MARGIN1) {
                const int x = atomicAdd(&g_fcnt[d], 1);
                if (x < MAXF) g_flags1[d * MAXF + x] = code | 1;
            }
        }
    }
    float4* pdst = reinterpret_cast<float4*>(pos_embed + (size_t)gw * NF);
    float4* ndst = reinterpret_cast<float4*>(neg_embed + (size_t)gw * NF);
    if (has_pos) {
        pdst[L] = reinterpret_cast<const float4*>(emb + ((size_t)d * NB + I1b) * NF)[L];
        ndst[L] = reinterpret_cast<const float4*>(emb + ((size_t)d * NB + J1b) * NF)[L];
    } else {
        const float4 z = make_float4(0.f, 0.f, 0.f, 0.f);
        pdst[L] = z; ndst[L] = z;
    }
}

// ---------------- L2: batched 3-pass MMA refine ----------------
__global__ __launch_bounds__(NTHREADS, 1)
void refine2_kernel() {
    extern __shared__ char smem[];
    const uint32_t sb = smem_u32(smem);
    const int tid = threadIdx.x;
    const int w = tid >> 5, L = tid & 31;
    const int wm = w & 3, wn = w >> 2;
    const int d = blockIdx.z, grp = blockIdx.x, slice = blockIdx.y;

    const int cnt = min(g_fcnt[d], MAXF);
    const int base = grp * 128;
    int nf = cnt - base;
    if (nf <= 0) return;
    if (nf > 128) nf = 128;

    const char* __restrict__ ghT =
        reinterpret_cast<const char*>(g_hi) + (size_t)d * DOMBYTES;
    const char* __restrict__ glT =
        reinterpret_cast<const char*>(g_lo) + (size_t)d * DOMBYTES;
    const int* __restrict__ labd = g_labels + d * NB;

    const uint32_t bar0 = sb + R_MB;
    if (tid == 0) { MBAR_INIT(bar0, 1); MBAR_INIT(bar0 + 8, 1); }
    FENCE_ASYNC();
    __syncthreads();

    const int t0 = slice * (NT / NSLICE);
    if (tid == 0) {
        MBAR_EXPECT(bar0, 2 * TILEBYTES);
        BULK_G2S(sb + R_B, ghT + (size_t)t0 * TILEBYTES, TILEBYTES, bar0);
        BULK_G2S(sb + R_B + TILEBYTES, glT + (size_t)t0 * TILEBYTES, TILEBYTES, bar0);
    }

    int* rows_s = reinterpret_cast<int*>(smem + R_ROWS);
    int* labs_s = reinterpret_cast<int*>(smem + R_LABS);
    if (tid < 128) {
        const int code = g_flags1[d * MAXF + base + ((tid < nf) ? tid : 0)];
        rows_s[tid] = code >> 1;
    }
    __syncthreads();
    if (tid < 128) labs_s[tid] = labd[rows_s[tid]];

#pragma unroll
    for (int it = 0; it < 8; ++it) {
        const int c = it * NTHREADS + tid;
        const int comp = c >> 11;
        const int rem = c & 2047;
        const int f = rem >> 4, kc = rem & 15;
        const int row = rows_s[f];
        const size_t srcb = (size_t)(row >> 7) * TILEBYTES + (size_t)(row & 127) * 256u
            + (((uint32_t)kc * 16u) ^ (((uint32_t)row & 7u) << 4));
        const uint4 v = *reinterpret_cast<const uint4*>((comp ? glT : ghT) + srcb);
        const uint32_t dstb = (uint32_t)f * 256u
            + (((uint32_t)kc * 16u) ^ (((uint32_t)f & 7u) << 4));
        *reinterpret_cast<uint4*>(smem + (comp ? R_AL : R_AH) + dstb) = v;
    }

    const uint32_t cxA = ((uint32_t)(L >> 4) * 16u) ^ (((uint32_t)L & 7u) << 4);
    const uint32_t cxB = ((uint32_t)((L >> 3) & 1) * 16u) ^ (((uint32_t)L & 7u) << 4);
    uint32_t aBase[2];
#pragma unroll
    for (int mt = 0; mt < 2; ++mt) {
        const int rowA = wm * 32 + mt * 16 + (L & 7) + ((L >> 3) & 1) * 8;
        aBase[mt] = sb + R_AH + (uint32_t)rowA * 256u;
    }
    uint32_t bRow[2];
#pragma unroll
    for (int bi = 0; bi < 2; ++bi) {
        const int rowB = wn * 32 + bi * 16 + (L & 7) + (L >> 4) * 8;
        bRow[bi] = (uint32_t)rowB * 256u;
    }

    const int rbase = wm * 32 + (L >> 2);
    int li[4], rid[4];
#pragma unroll
    for (int s = 0; s < 4; ++s) {
        const int f = rbase + (s & 1) * 8 + (s >> 1) * 16;
        li[s] = labs_s[f];
        rid[s] = rows_s[f];
    }
    __syncthreads();

    const float INF = __int_as_float(0x7f800000);
    float p1[4], p2[4], n1[4], n2[4];
    int i1[4], j1[4];
#pragma unroll
    for (int s = 0; s < 4; ++s) {
        p1[s] = INF; p2[s] = INF; n1[s] = -INF; n2[s] = -INF;
        i1[s] = -1; j1[s] = -1;
    }

    for (int tt = 0; tt < NT / NSLICE; ++tt) {
        const int t = t0 + tt;
        if (tt + 1 < NT / NSLICE && tid == 0) {
            const uint32_t bn_ = bar0 + (uint32_t)((tt + 1) & 1) * 8u;
            const uint32_t bo = sb + R_B + (uint32_t)((tt + 1) & 1) * 65536u;
            MBAR_EXPECT(bn_, 2 * TILEBYTES);
            BULK_G2S(bo, ghT + (size_t)(t + 1) * TILEBYTES, TILEBYTES, bn_);
            BULK_G2S(bo + TILEBYTES, glT + (size_t)(t + 1) * TILEBYTES, TILEBYTES, bn_);
        }
        MBAR_WAIT(bar0 + (uint32_t)(tt & 1) * 8u, (tt >> 1) & 1);

        const int jb = t * BN + wn * 32 + (L & 3) * 2;
        int labc[4][2];
#pragma unroll
        for (int nt = 0; nt < 4; ++nt) {
            const int2 lv = *reinterpret_cast<const int2*>(labd + jb + nt * 8);
            labc[nt][0] = lv.x; labc[nt][1] = lv.y;
        }

        float acc[2][4][4];
#pragma unroll
        for (int mt = 0; mt < 2; ++mt)
#pragma unroll
            for (int nt = 0; nt < 4; ++nt)
#pragma unroll
                for (int r = 0; r < 4; ++r) acc[mt][nt][r] = 0.0f;

        const uint32_t sbB = sb + R_B + (uint32_t)(tt & 1) * 65536u;
#pragma unroll
        for (int ks = 0; ks < 8; ++ks) {
            const uint32_t offA = ((uint32_t)ks * 32u) ^ cxA;
            const uint32_t offB = ((uint32_t)ks * 32u) ^ cxB;
            uint32_t Ah[2][4], Al[2][4], Bh[2][4], Bl[2][4];
            ldsm4(Ah[0], aBase[0] + offA);
            ldsm4(Ah[1], aBase[1] + offA);
            ldsm4(Bh[0], sbB + bRow[0] + offB);
            ldsm4(Bh[1], sbB + bRow[1] + offB);
            ldsm4(Al[0], aBase[0] + 32768u + offA);
            ldsm4(Al[1], aBase[1] + 32768u + offA);
            ldsm4(Bl[0], sbB + TILEBYTES + bRow[0] + offB);
            ldsm4(Bl[1], sbB + TILEBYTES + bRow[1] + offB);
#pragma unroll
            for (int bi = 0; bi < 2; ++bi)
#pragma unroll
                for (int mt = 0; mt < 2; ++mt) {
                    mma16816(acc[mt][2 * bi],     Ah[mt], Bh[bi]);
                    mma16816(acc[mt][2 * bi + 1], Ah[mt], Bh[bi] + 2);
                }
#pragma unroll
            for (int bi = 0; bi < 2; ++bi)
#pragma unroll
                for (int mt = 0; mt < 2; ++mt) {
                    mma16816(acc[mt][2 * bi],     Al[mt], Bh[bi]);
                    mma16816(acc[mt][2 * bi + 1], Al[mt], Bh[bi] + 2);
                }
#pragma unroll
            for (int bi = 0; bi < 2; ++bi)
#pragma unroll
                for (int mt = 0; mt < 2; ++mt) {
                    mma16816(acc[mt][2 * bi],     Ah[mt], Bl[bi]);
                    mma16816(acc[mt][2 * bi + 1], Ah[mt], Bl[bi] + 2);
                }
        }

#pragma unroll
        for (int nt = 0; nt < 4; ++nt)
#pragma unroll
            for (int e = 0; e < 2; ++e) {
                const int lj = labc[nt][e];
                const int j = jb + nt * 8 + e;
#pragma unroll
                for (int s = 0; s < 4; ++s) {
                    const float v = acc[s >> 1][nt][(s & 1) * 2 + e];
                    if (lj == li[s]) {
                        if (j != rid[s]) {
                            if (v < p1[s]) { p2[s] = p1[s]; p1[s] = v; i1[s] = j; }
                            else if (v < p2[s]) p2[s] = v;
                        }
                    } else {
                        if (v > n1[s]) { n2[s] = n1[s]; n1[s] = v; j1[s] = j; }
                        else if (v > n2[s]) n2[s] = v;
                    }
                }
            }
        __syncthreads();
    }

#pragma unroll
    for (int s = 0; s < 4; ++s) {
#pragma unroll
        for (int off = 1; off <= 2; off <<= 1) {
            const float q1 = __shfl_xor_sync(~0u, p1[s], off);
            const float q2 = __shfl_xor_sync(~0u, p2[s], off);
            const int   qi = __shfl_xor_sync(~0u, i1[s], off);
            const float m1 = __shfl_xor_sync(~0u, n1[s], off);
            const float m2 = __shfl_xor_sync(~0u, n2[s], off);
            const int   mi = __shfl_xor_sync(~0u, j1[s], off);
            MERGE_MIN(p1[s], p2[s], i1[s], q1, q2, qi);
            MERGE_MAX(n1[s], n2[s], j1[s], m1, m2, mi);
        }
    }

    float* scr = reinterpret_cast<float*>(smem + R_SCR);
    if (wn > 0 && (L & 3) == 0) {
#pragma unroll
        for (int s = 0; s < 4; ++s) {
            const int f = rbase + (s & 1) * 8 + (s >> 1) * 16;
            float* sr = scr + (f * 4 + wn) * 8;
            sr[0] = p1[s]; sr[1] = p2[s];
            reinterpret_cast<int*>(sr)[2] = i1[s];
            sr[3] = n1[s]; sr[4] = n2[s];
            reinterpret_cast<int*>(sr)[5] = j1[s];
        }
    }
    __syncthreads();
    if (wn == 0 && (L & 3) == 0) {
#pragma unroll
        for (int s = 0; s < 4; ++s) {
            const int f = rbase + (s & 1) * 8 + (s >> 1) * 16;
            float P1 = p1[s], P2 = p2[s], N1 = n1[s], N2 = n2[s];
            int I1 = i1[s], J1 = j1[s];
#pragma unroll
            for (int o = 1; o < 4; ++o) {
                const float* sr = scr + (f * 4 + o) * 8;
                MERGE_MIN(P1, P2, I1, sr[0], sr[1], reinterpret_cast<const int*>(sr)[2]);
                MERGE_MAX(N1, N2, J1, sr[3], sr[4], reinterpret_cast<const int*>(sr)[5]);
            }
            if (f < nf) {
                float4* dst = reinterpret_cast<float4*>(
                    g_rp + (((size_t)d * MAXF + base + f) * NSLICE + slice) * 8);
                dst[0] = make_float4(P1, P2, __int_as_float(I1), N1);
                dst[1] = make_float4(N2, __int_as_float(J1), 0.f, 0.f);
            }
        }
    }
}

// ---------------- L2 merge: fold 16 slices, write outputs, cascade to L3 ----------------
__global__ void refine2_merge(const float* __restrict__ emb,
                              float* __restrict__ pos_dist,
                              float* __restrict__ neg_dist,
                              float* __restrict__ pos_embed,
                              float* __restrict__ neg_embed) {
    const int wid = threadIdx.x >> 5, L = threadIdx.x & 31;
    const int d = blockIdx.y;
    const int x = blockIdx.x * 8 + wid;
    const int cnt = min(g_fcnt[d], MAXF);
    if (x >= cnt) return;
    const int code = g_flags1[d * MAXF + x];
    const int row = code >> 1, side = code & 1;

    const float4* bp = reinterpret_cast<const float4*>(
        g_rp + (((size_t)d * MAXF + x) * NSLICE + (L & 15)) * 8);
    const float4 a = bp[0], b = bp[1];
    float P1 = a.x, P2 = a.y, N1 = a.w, N2 = b.x;
    int I1 = __float_as_int(a.z), J1 = __float_as_int(b.y);
#pragma unroll
    for (int off = 1; off <= 8; off <<= 1) {
        const float q1 = __shfl_xor_sync(~0u, P1, off);
        const float q2 = __shfl_xor_sync(~0u, P2, off);
        const int   qi = __shfl_xor_sync(~0u, I1, off);
        const float m1 = __shfl_xor_sync(~0u, N1, off);
        const float m2 = __shfl_xor_sync(~0u, N2, off);
        const int   mi = __shfl_xor_sync(~0u, J1, off);
        MERGE_MIN(P1, P2, I1, q1, q2, qi);
        MERGE_MAX(N1, N2, J1, m1, m2, mi);
    }
    float v1 = side ? N1 : P1;
    float gap = side ? (N1 - N2) : (P2 - P1);
    int idx = side ? J1 : I1;
    v1  = __shfl_sync(~0u, v1, 0);
    gap = __shfl_sync(~0u, gap, 0);
    idx = __shfl_sync(~0u, idx, 0);
    if (idx < 0) return;

    const size_t go = (size_t)d * NB + row;
    if (L == 0) {
        (side ? neg_dist : pos_dist)[go] = v1;
        if (gap < MARGIN2) {
            const int y = atomicAdd(&g_fcnt3, 1);
            if (y < MAXF3) g_flags3[y] = (int)((go << 1) | (size_t)side);
        }
    }
    float4* dst = reinterpret_cast<float4*>(
        (side ? neg_embed : pos_embed) + go * NF);
    dst[L] = reinterpret_cast<const float4*>(
        emb + ((size_t)d * NB + idx) * NF)[L];
}

// ---------------- L3: exact fp32 full-row rescan (rare) ----------------
__global__ void refine3_scan(const float* __restrict__ emb) {
    __shared__ float srow[NF];
    __shared__ int sli;
    __shared__ unsigned long long swb[8];
    const int cnt = min(g_fcnt3, MAXF3);
    for (int f = blockIdx.x; f < cnt; f += gridDim.x) {
        const int code = g_flags3[f];
        const int side = code & 1, gr = code >> 1;
        const int d = gr >> 13, row = gr & (NB - 1);
        const float* __restrict__ embd = emb + (size_t)d * NB * NF;
        __syncthreads();
        if (threadIdx.x < NF) srow[threadIdx.x] = embd[(size_t)row * NF + threadIdx.x];
        if (threadIdx.x == 0) sli = g_labels[d * NB + row];
        __syncthreads();
        const int li = sli;
        const float4* a4 = reinterpret_cast<const float4*>(srow);

        unsigned long long best = 0ull;
        for (int j = threadIdx.x; j < NB; j += blockDim.x) {
            const int lj = g_labels[d * NB + j];
            const bool valid = side ? (lj != li) : (lj == li && j != row);
            if (!valid) continue;
            const float4* b4 = reinterpret_cast<const float4*>(embd + (size_t)j * NF);
            float accv = 0.0f;
#pragma unroll
            for (int qq = 0; qq < 32; ++qq) {
                const float4 av = a4[qq], bv = b4[qq];
                accv = fmaf(av.x, bv.x, accv);
                accv = fmaf(av.y, bv.y, accv);
                accv = fmaf(av.z, bv.z, accv);
                accv = fmaf(av.w, bv.w, accv);
            }
            uint32_t key = fkey(accv);
            if (!side) key = ~key;
            const unsigned long long pk =
                ((unsigned long long)key << 32) | (uint32_t)(NB - 1 - j);
            if (pk > best) best = pk;
        }
#pragma unroll
        for (int off = 16; off > 0; off >>= 1) {
            const unsigned long long o = __shfl_xor_sync(~0u, best, off);
            if (o > best) best = o;
        }
        if ((threadIdx.x & 31) == 0) swb[threadIdx.x >> 5] = best;
        __syncthreads();
        if (threadIdx.x == 0) {
            unsigned long long b = swb[0];
#pragma unroll
            for (int o = 1; o < 8; ++o) if (swb[o] > b) b = swb[o];
            g_best[f] = b;
        }
    }
}

__global__ void refine3_write(const float* __restrict__ emb,
                              float* __restrict__ pos_dist,
                              float* __restrict__ neg_dist,
                              float* __restrict__ pos_embed,
                              float* __restrict__ neg_embed) {
    const int cnt = min(g_fcnt3, MAXF3);
    for (int f = blockIdx.x; f < cnt; f += gridDim.x) {
        const int code = g_flags3[f];
        const int side = code & 1, gr = code >> 1;
        const int d = gr >> 13, row = gr & (NB - 1);
        const unsigned long long pk = g_best[f];
        if (pk == 0ull) continue;
        const uint32_t key = (uint32_t)(pk >> 32);
        const int j = NB - 1 - (int)(pk & 0xFFFFFFFFull);
        const uint32_t m = side ? key : ~key;
        const uint32_t u = (m & 0x80000000u) ? (m & 0x7FFFFFFFu) : ~m;
        const float v = __uint_as_float(u);

        const size_t go = (size_t)d * NB + row;
        float* dist = side ? neg_dist : pos_dist;
        float* embo = side ? neg_embed : pos_embed;
        if (threadIdx.x == 0) dist[go] = v;
        embo[go * NF + threadIdx.x] = emb[((size_t)d * NB + j) * NF + threadIdx.x];
    }
}

// ---------------- launch ----------------
extern "C" void kernel_launch(void* const* d_in, const int* in_sizes, int n_in,
                              void* d_out, int out_size) {
    (void)in_sizes; (void)n_in; (void)out_size;
    const float* emb = (const float*)d_in[0];
    const unsigned int* labw = (const unsigned int*)d_in[1];

    float* out = (float*)d_out;
    float* pos_dist  = out;
    float* neg_dist  = out + (size_t)NDOM * NB;
    float* pos_embed = out + (size_t)2 * NDOM * NB;
    float* neg_embed = pos_embed + (size_t)NDOM * NB * NF;

    convert_labels_kernel<<<1, 256>>>(labw, NDOM * NB);
    split_kernel<<<(NDOM * NB * NF / 4) / 256, 256>>>(emb);

    cudaFuncSetAttribute(mine_kernel,
                         cudaFuncAttributeMaxDynamicSharedMemorySize, SMEM_BYTES);
    mine_kernel<<<NDOM * 256, NTHREADS, SMEM_BYTES>>>();

    merge_kernel<<<(NDOM * NB * 32) / 256, 256>>>(emb, pos_dist, neg_dist,
                                                  pos_embed, neg_embed);

    cudaFuncSetAttribute(refine2_kernel,
                         cudaFuncAttributeMaxDynamicSharedMemorySize, SMEM2_BYTES);
    dim3 rgrid(MAXF / 128, NSLICE, NDOM);
    refine2_kernel<<<rgrid, NTHREADS, SMEM2_BYTES>>>();

    dim3 mgrid(MAXF / 8, NDOM);
    refine2_merge<<<mgrid, 256>>>(emb, pos_dist, neg_dist, pos_embed, neg_embed);

    refine3_scan<<<128, 256>>>(emb);
    refine3_write<<<64, NF>>>(emb, pos_dist, neg_dist, pos_embed, neg_embed);
}